// round 14
// baseline (speedup 1.0000x reference)
#include <cuda_runtime.h>
#include <cuda_fp16.h>
#include <math.h>
#include <stdint.h>

typedef __half fp16;

#define NTOK 8192
#define DIMC 1024
#define HIDC 2048
#define NRE  6
#define E2   (2ull<<20)

#define W1S_OFF 0ull
#define W3S_OFF (4ull<<20)
#define W2S_OFF (8ull<<20)
#define W1R_OFF (12ull<<20)
#define W3R_OFF (24ull<<20)
#define W2R_OFF (36ull<<20)
#define OUTW_OFF (48ull<<20)
#define WT_TOTAL (49ull<<20)

__device__ fp16 g_wt[WT_TOTAL];                      // weights fp16 [N][K]
__device__ fp16 g_x[(size_t)NTOK * DIMC];            // activations fp16
__device__ fp16 g_hall[8ull * NTOK * HIDC];          // h per expert slice
__device__ float g_comb[(size_t)NTOK * DIMC];        // shared experts (fused sum)
__device__ float g_bufA[(size_t)NTOK * DIMC];        // routed top-1
__device__ float g_bufB[(size_t)NTOK * DIMC];        // routed top-2
__device__ fp16 g_hc[(size_t)NTOK * DIMC];           // combined fp16
__device__ int   g_list[NRE * NTOK];
__device__ float g_lw[NRE * NTOK];
__device__ int   g_lrank[NRE * NTOK];
__device__ int   g_cnt[NRE];
__device__ int   g_top1[NRE];
__device__ float g_psum[NRE];

// ===================== helpers =====================
__device__ __forceinline__ uint32_t s2u(const void* p) {
    return (uint32_t)__cvta_generic_to_shared(p);
}
__device__ __forceinline__ void cpa(uint32_t s, const void* g) {
    asm volatile("cp.async.cg.shared.global [%0], [%1], 16;" :: "r"(s), "l"(g));
}
__device__ __forceinline__ void cpa_commit() {
    asm volatile("cp.async.commit_group;" ::: "memory");
}
__device__ __forceinline__ void ldsm4(uint32_t* r, uint32_t addr) {
    asm volatile("ldmatrix.sync.aligned.m8n8.x4.shared.b16 {%0,%1,%2,%3}, [%4];"
        : "=r"(r[0]), "=r"(r[1]), "=r"(r[2]), "=r"(r[3]) : "r"(addr));
}
__device__ __forceinline__ void mma16816(float* d, const uint32_t* a, const uint32_t* b) {
    asm volatile("mma.sync.aligned.m16n8k16.row.col.f32.f16.f16.f32 "
        "{%0,%1,%2,%3}, {%4,%5,%6,%7}, {%8,%9}, {%0,%1,%2,%3};"
        : "+f"(d[0]), "+f"(d[1]), "+f"(d[2]), "+f"(d[3])
        : "r"(a[0]), "r"(a[1]), "r"(a[2]), "r"(a[3]), "r"(b[0]), "r"(b[1]));
}

// ===================== small kernels =====================
__global__ void __launch_bounds__(256) convx_kernel(const float* __restrict__ x) {
    if (blockIdx.x == 0 && threadIdx.x < NRE) {
        g_cnt[threadIdx.x] = 0; g_top1[threadIdx.x] = 0; g_psum[threadIdx.x] = 0.f;
    }
    size_t i = ((size_t)blockIdx.x * 256 + threadIdx.x) * 8;
    float4 v0 = *(const float4*)(x + i);
    float4 v1 = *(const float4*)(x + i + 4);
    uint4 o;
    o.x = *(uint32_t*)&__floats2half2_rn(v0.x, v0.y);
    o.y = *(uint32_t*)&__floats2half2_rn(v0.z, v0.w);
    o.z = *(uint32_t*)&__floats2half2_rn(v1.x, v1.y);
    o.w = *(uint32_t*)&__floats2half2_rn(v1.z, v1.w);
    *(uint4*)(g_x + i) = o;
}

__global__ void __launch_bounds__(256) gate_kernel(const float* __restrict__ x,
                                                   const float* __restrict__ gw) {
    __shared__ float sgw[DIMC * NRE];
    int tid = threadIdx.x;
    for (int i = tid; i < DIMC * NRE; i += 256) sgw[i] = gw[i];
    __syncthreads();
    int warp = tid >> 5, lane = tid & 31;
    int token = blockIdx.x * 8 + warp;
    if (token >= NTOK) return;
    const float* xr = x + (size_t)token * DIMC;
    float acc[NRE] = {0.f, 0.f, 0.f, 0.f, 0.f, 0.f};
    for (int k = lane; k < DIMC; k += 32) {
        float xv = xr[k];
#pragma unroll
        for (int e = 0; e < NRE; e++) acc[e] += xv * sgw[k * NRE + e];
    }
#pragma unroll
    for (int e = 0; e < NRE; e++)
#pragma unroll
        for (int o = 16; o > 0; o >>= 1)
            acc[e] += __shfl_xor_sync(0xffffffffu, acc[e], o);
    if (lane == 0) {
        int i0 = 0; float v0 = acc[0];
        for (int e = 1; e < NRE; e++) if (acc[e] > v0) { v0 = acc[e]; i0 = e; }
        int i1 = -1; float v1 = -1e30f;
        for (int e = 0; e < NRE; e++) if (e != i0 && acc[e] > v1) { v1 = acc[e]; i1 = e; }
        float e2 = expf(v1 - v0);
        float inv = 1.0f / (1.0f + e2);
        float w0 = inv, w1 = e2 * inv;
        float p[NRE]; float s = 0.f;
        for (int e = 0; e < NRE; e++) { p[e] = expf(acc[e] - v0); s += p[e]; }
        float is = 1.0f / s;
        for (int e = 0; e < NRE; e++) atomicAdd(&g_psum[e], p[e] * is);
        atomicAdd(&g_top1[i0], 1);
        int p0 = atomicAdd(&g_cnt[i0], 1);
        g_list[i0 * NTOK + p0] = token; g_lw[i0 * NTOK + p0] = w0; g_lrank[i0 * NTOK + p0] = 0;
        int p1 = atomicAdd(&g_cnt[i1], 1);
        g_list[i1 * NTOK + p1] = token; g_lw[i1 * NTOK + p1] = w1; g_lrank[i1 * NTOK + p1] = 1;
    }
}

__global__ void __launch_bounds__(256) convt_all_kernel(
    const float* w1_s, const float* w3_s, const float* w2_s,
    const float* w1_r, const float* w3_r, const float* w2_r,
    const float* out_w)
{
    __shared__ float t[32][33];
    int z = blockIdx.z;
    int K, N; const float* src; fp16* dst;
    if (z < 16) {
        K = DIMC; N = HIDC;
        if (z < 2)       { src = w1_s + (size_t)z * E2;        dst = g_wt + W1S_OFF + (size_t)z * E2; }
        else if (z < 4)  { int e = z - 2;  src = w3_s + (size_t)e * E2; dst = g_wt + W3S_OFF + (size_t)e * E2; }
        else if (z < 10) { int e = z - 4;  src = w1_r + (size_t)e * E2; dst = g_wt + W1R_OFF + (size_t)e * E2; }
        else             { int e = z - 10; src = w3_r + (size_t)e * E2; dst = g_wt + W3R_OFF + (size_t)e * E2; }
    } else if (z < 24) {
        K = HIDC; N = DIMC;
        if (z < 18) { int e = z - 16; src = w2_s + (size_t)e * E2; dst = g_wt + W2S_OFF + (size_t)e * E2; }
        else        { int e = z - 18; src = w2_r + (size_t)e * E2; dst = g_wt + W2R_OFF + (size_t)e * E2; }
    } else {
        K = DIMC; N = DIMC; src = out_w; dst = g_wt + OUTW_OFF;
    }
    int k0 = blockIdx.y * 32, n0 = blockIdx.x * 32;
    if (k0 >= K || n0 >= N) return;
    int tx = threadIdx.x & 31, ty = threadIdx.x >> 5;
#pragma unroll
    for (int i = 0; i < 4; i++)
        t[ty + i * 8][tx] = src[(size_t)(k0 + ty + i * 8) * N + n0 + tx];
    __syncthreads();
#pragma unroll
    for (int i = 0; i < 4; i++)
        dst[(size_t)(n0 + ty + i * 8) * K + k0 + tx] = __float2half_rn(t[tx][ty + i * 8]);
}

// comb + bufA + bufB -> fp16 ; block 0 thread 0 also writes aux loss
__global__ void __launch_bounds__(256) convc3_kernel(float* auxDst) {
    if (auxDst && blockIdx.x == 0 && threadIdx.x == 0) {
        float a = 0.f;
        for (int e = 0; e < NRE; e++) {
            float f = (float)g_top1[e] / (float)NTOK;
            float pm = g_psum[e] / (float)NTOK;
            a += f * pm;
        }
        *auxDst = 0.01f * (float)NRE * a;
    }
    size_t i = ((size_t)blockIdx.x * 256 + threadIdx.x) * 2;
    float2 a = *(const float2*)(g_comb + i);
    float2 b = *(const float2*)(g_bufA + i);
    float2 c = *(const float2*)(g_bufB + i);
    *(uint32_t*)(g_hc + i) = *(uint32_t*)&__floats2half2_rn(a.x + b.x + c.x,
                                                            a.y + b.y + c.y);
}

// ===================== mm1_all: all 8 pass-1 GEMMs =====================
// tile 256M x 64N dual(B1,B3), chunk K=64, 3-stage, 512 threads,
// warps 8(M)x2(N), warp tile 32x32 per matrix (64 acc regs)
#define P1_PITCH 144
#define P1_A  0
#define P1_B1 36864
#define P1_B3 46080
#define P1_STG 55296
#define P1_SIDX (3*P1_STG)           // 165888
#define P1_SMEM (P1_SIDX + 1024)     // 166912

__global__ void __launch_bounds__(512, 1) mm1_all_kernel()
{
    extern __shared__ char smem[];
    const int z = blockIdx.z;
    const fp16* W1; const fp16* W3;
    const int* gidx; const float* gscale; int M;
    if (z < 2) {
        W1 = g_wt + W1S_OFF + (size_t)z * E2;
        W3 = g_wt + W3S_OFF + (size_t)z * E2;
        gidx = nullptr; gscale = nullptr; M = NTOK;
    } else {
        int e = z - 2;
        W1 = g_wt + W1R_OFF + (size_t)e * E2;
        W3 = g_wt + W3R_OFF + (size_t)e * E2;
        gidx = g_list + e * NTOK; gscale = g_lw + e * NTOK; M = g_cnt[e];
    }
    fp16* hout = g_hall + (size_t)z * NTOK * HIDC;

    const int mBase = blockIdx.y * 256;
    if (mBase >= M) return;
    const int nBase = blockIdx.x * 64;
    const uint32_t sb = s2u(smem);
    const int tid = threadIdx.x;

    int* sIdx = (int*)(smem + P1_SIDX);
    if (tid < 256) {
        int r = mBase + tid;
        sIdx[tid] = (r < M) ? (gidx ? gidx[r] : r) : 0;
    }
    __syncthreads();

    auto load = [&](int buf, int k0) {
        uint32_t su = sb + buf * P1_STG;
#pragma unroll
        for (int it = 0; it < 4; it++) {
            int idx = tid + it * 512;
            int row = idx >> 3, seg = idx & 7;         // row in [0,256)
            uint32_t so = row * P1_PITCH + seg * 16;
            cpa(su + P1_A + so, g_x + (size_t)sIdx[row] * DIMC + k0 + seg * 8);
        }
        {
            int row = tid >> 3, seg = tid & 7;          // tid<512 -> row in [0,64)
            uint32_t so = row * P1_PITCH + seg * 16;
            size_t gw = (size_t)(nBase + row) * DIMC + k0 + seg * 8;
            cpa(su + P1_B1 + so, W1 + gw);
            cpa(su + P1_B3 + so, W3 + gw);
        }
        cpa_commit();
    };

    const int lane = tid & 31, wid = tid >> 5;          // wid 0..15
    const int wm = (wid & 7) * 32;                      // 8 m-warps
    const int wn = (wid >> 3) * 32;                     // 2 n-warps
    const int arow = (lane & 7) + ((lane >> 3) & 1) * 8;
    const int akh  = (lane >> 4) & 1;
    const int brow = (lane & 7) + ((lane >> 4) & 1) * 8;
    const int bkh  = (lane >> 3) & 1;

    float acc1[2][4][4], acc3[2][4][4];
#pragma unroll
    for (int i = 0; i < 2; i++)
#pragma unroll
        for (int j = 0; j < 4; j++)
#pragma unroll
            for (int k = 0; k < 4; k++) { acc1[i][j][k] = 0.f; acc3[i][j][k] = 0.f; }

    const int nc = DIMC / 64;   // 16
    load(0, 0);
    load(1, 64);
    for (int c = 0; c < nc; c++) {
        if (c + 1 < nc) asm volatile("cp.async.wait_group 1;" ::: "memory");
        else            asm volatile("cp.async.wait_group 0;" ::: "memory");
        __syncthreads();
        if (c + 2 < nc) load((c + 2) % 3, (c + 2) * 64);
        uint32_t su = sb + (c % 3) * P1_STG;
#pragma unroll
        for (int s = 0; s < 4; s++) {
            uint32_t a[2][4];
#pragma unroll
            for (int mi = 0; mi < 2; mi++) {
                uint32_t ao = (uint32_t)(wm + mi * 16 + arow) * P1_PITCH + s * 32 + akh * 16;
                ldsm4(a[mi], su + P1_A + ao);
            }
#pragma unroll
            for (int np = 0; np < 2; np++) {
                uint32_t b1[4], b3[4];
                uint32_t bo = (uint32_t)(wn + np * 16 + brow) * P1_PITCH + s * 32 + bkh * 16;
                ldsm4(b1, su + P1_B1 + bo);
                ldsm4(b3, su + P1_B3 + bo);
#pragma unroll
                for (int mi = 0; mi < 2; mi++)
#pragma unroll
                    for (int h = 0; h < 2; h++) {
                        int nt = np * 2 + h;
                        mma16816(acc1[mi][nt], a[mi], &b1[h * 2]);
                        mma16816(acc3[mi][nt], a[mi], &b3[h * 2]);
                    }
            }
        }
    }

#pragma unroll
    for (int mi = 0; mi < 2; mi++)
#pragma unroll
        for (int half = 0; half < 2; half++) {
            int slot = mBase + wm + mi * 16 + (lane >> 2) + half * 8;
            if (slot < M) {
                float sc = gscale ? gscale[slot] : 1.0f;
                size_t rb = (size_t)slot * HIDC + nBase + wn + (lane & 3) * 2;
#pragma unroll
                for (int nt = 0; nt < 4; nt++) {
                    float u0 = acc1[mi][nt][half * 2 + 0];
                    float u1 = acc1[mi][nt][half * 2 + 1];
                    float v0 = acc3[mi][nt][half * 2 + 0];
                    float v1 = acc3[mi][nt][half * 2 + 1];
                    float h0 = u0 / (1.f + __expf(-u0)) * v0 * sc;
                    float h1 = u1 / (1.f + __expf(-u1)) * v1 * sc;
                    __half2 hp = __floats2half2_rn(h0, h1);
                    *(uint32_t*)(hout + rb + nt * 8) = *(uint32_t*)&hp;
                }
            }
        }
}

// ===================== mm2_all: 7 z-slices (128x128, chunk 64, 3-stage, occ 2) =====================
// z 0: BOTH shared experts (acc carried across two K-loops) -> comb.
// z 1..6: routed expert e=z-1 -> bufA/bufB by rank.
#define P2_A 0
#define P2_B 18432
#define P2_STG 36864
#define P2_SMEM (3*P2_STG)   // 110592

__global__ void __launch_bounds__(256, 2) mm2_all_kernel()
{
    extern __shared__ char smem[];
    const int z = blockIdx.z;
    const int e = z - 1;
    const int nPass = (z == 0) ? 2 : 1;
    const int M = (z == 0) ? NTOK : g_cnt[e];
    const int mBase = blockIdx.y * 128;
    if (mBase >= M) return;
    const int nBase = blockIdx.x * 128;
    const uint32_t sb = s2u(smem);
    const int tid = threadIdx.x;

    const int lane = tid & 31, wid = tid >> 5;
    const int wm = (wid & 1) * 64;
    const int wn = (wid >> 1) * 32;
    const int arow = (lane & 7) + ((lane >> 3) & 1) * 8;
    const int akh  = (lane >> 4) & 1;
    const int brow = (lane & 7) + ((lane >> 4) & 1) * 8;
    const int bkh  = (lane >> 3) & 1;

    float acc[4][4][4];
#pragma unroll
    for (int i = 0; i < 4; i++)
#pragma unroll
        for (int j = 0; j < 4; j++)
#pragma unroll
            for (int k = 0; k < 4; k++) acc[i][j][k] = 0.f;

    for (int ss = 0; ss < nPass; ss++) {
        const fp16* A; const fp16* B;
        if (z == 0) {
            A = g_hall + (size_t)ss * NTOK * HIDC;
            B = g_wt + W2S_OFF + (size_t)ss * E2;
        } else {
            A = g_hall + (size_t)(2 + e) * NTOK * HIDC;
            B = g_wt + W2R_OFF + (size_t)e * E2;
        }
        auto load = [&](int buf, int k0) {
            uint32_t su = sb + buf * P2_STG;
#pragma unroll
            for (int it = 0; it < 4; it++) {
                int idx = tid + it * 256;
                int row = idx >> 3, seg = idx & 7;
                uint32_t so = row * 144 + seg * 16;
                int ar = mBase + row; if (ar >= M) ar = mBase;
                cpa(su + P2_A + so, A + (size_t)ar * HIDC + k0 + seg * 8);
                cpa(su + P2_B + so, B + (size_t)(nBase + row) * HIDC + k0 + seg * 8);
            }
            cpa_commit();
        };
        const int nc = HIDC / 64;
        load(0, 0);
        load(1, 64);
        for (int c = 0; c < nc; c++) {
            if (c + 1 < nc) asm volatile("cp.async.wait_group 1;" ::: "memory");
            else            asm volatile("cp.async.wait_group 0;" ::: "memory");
            __syncthreads();
            if (c + 2 < nc) load((c + 2) % 3, (c + 2) * 64);
            uint32_t su = sb + (c % 3) * P2_STG;
#pragma unroll
            for (int s = 0; s < 4; s++) {
                uint32_t a[4][4];
#pragma unroll
                for (int mi = 0; mi < 4; mi++) {
                    uint32_t ao = (uint32_t)(wm + mi * 16 + arow) * 144 + s * 32 + akh * 16;
                    ldsm4(a[mi], su + P2_A + ao);
                }
#pragma unroll
                for (int np = 0; np < 2; np++) {
                    uint32_t b[4];
                    uint32_t bo = (uint32_t)(wn + np * 16 + brow) * 144 + s * 32 + bkh * 16;
                    ldsm4(b, su + P2_B + bo);
#pragma unroll
                    for (int mi = 0; mi < 4; mi++)
#pragma unroll
                        for (int h = 0; h < 2; h++)
                            mma16816(acc[mi][np * 2 + h], a[mi], &b[h * 2]);
                }
            }
        }
        __syncthreads();
    }

#pragma unroll
    for (int mi = 0; mi < 4; mi++)
#pragma unroll
        for (int half = 0; half < 2; half++) {
            int slot = mBase + wm + mi * 16 + (lane >> 2) + half * 8;
            if (slot < M) {
                float* base; int t;
                if (z == 0) { base = g_comb; t = slot; }
                else {
                    t = g_list[e * NTOK + slot];
                    base = g_lrank[e * NTOK + slot] ? g_bufB : g_bufA;
                }
                float* cp = base + (size_t)t * DIMC + nBase + wn + (lane & 3) * 2;
#pragma unroll
                for (int nt = 0; nt < 4; nt++)
                    *(float2*)(cp + nt * 8) = make_float2(acc[mi][nt][half * 2 + 0],
                                                          acc[mi][nt][half * 2 + 1]);
            }
        }
}

// outproj: out = g_hc @ outw (K=1024)
__global__ void __launch_bounds__(256, 2) outproj_kernel(float* __restrict__ out)
{
    extern __shared__ char smem[];
    const int mBase = blockIdx.y * 128;
    const int nBase = blockIdx.x * 128;
    const fp16* B = g_wt + OUTW_OFF;
    const uint32_t sb = s2u(smem);
    const int tid = threadIdx.x;

    auto load = [&](int buf, int k0) {
        uint32_t su = sb + buf * P2_STG;
#pragma unroll
        for (int it = 0; it < 4; it++) {
            int idx = tid + it * 256;
            int row = idx >> 3, seg = idx & 7;
            uint32_t so = row * 144 + seg * 16;
            cpa(su + P2_A + so, g_hc + (size_t)(mBase + row) * DIMC + k0 + seg * 8);
            cpa(su + P2_B + so, B + (size_t)(nBase + row) * DIMC + k0 + seg * 8);
        }
        cpa_commit();
    };

    const int lane = tid & 31, wid = tid >> 5;
    const int wm = (wid & 1) * 64;
    const int wn = (wid >> 1) * 32;
    const int arow = (lane & 7) + ((lane >> 3) & 1) * 8;
    const int akh  = (lane >> 4) & 1;
    const int brow = (lane & 7) + ((lane >> 4) & 1) * 8;
    const int bkh  = (lane >> 3) & 1;

    float acc[4][4][4];
#pragma unroll
    for (int i = 0; i < 4; i++)
#pragma unroll
        for (int j = 0; j < 4; j++)
#pragma unroll
            for (int k = 0; k < 4; k++) acc[i][j][k] = 0.f;

    const int nc = DIMC / 64;
    load(0, 0);
    load(1, 64);
    for (int c = 0; c < nc; c++) {
        if (c + 1 < nc) asm volatile("cp.async.wait_group 1;" ::: "memory");
        else            asm volatile("cp.async.wait_group 0;" ::: "memory");
        __syncthreads();
        if (c + 2 < nc) load((c + 2) % 3, (c + 2) * 64);
        uint32_t su = sb + (c % 3) * P2_STG;
#pragma unroll
        for (int s = 0; s < 4; s++) {
            uint32_t a[4][4];
#pragma unroll
            for (int mi = 0; mi < 4; mi++) {
                uint32_t ao = (uint32_t)(wm + mi * 16 + arow) * 144 + s * 32 + akh * 16;
                ldsm4(a[mi], su + P2_A + ao);
            }
#pragma unroll
            for (int np = 0; np < 2; np++) {
                uint32_t b[4];
                uint32_t bo = (uint32_t)(wn + np * 16 + brow) * 144 + s * 32 + bkh * 16;
                ldsm4(b, su + P2_B + bo);
#pragma unroll
                for (int mi = 0; mi < 4; mi++)
#pragma unroll
                    for (int h = 0; h < 2; h++)
                        mma16816(acc[mi][np * 2 + h], a[mi], &b[h * 2]);
            }
        }
    }

#pragma unroll
    for (int mi = 0; mi < 4; mi++)
#pragma unroll
        for (int half = 0; half < 2; half++) {
            int t = mBase + wm + mi * 16 + (lane >> 2) + half * 8;
            float* cp = out + (size_t)t * DIMC + nBase + wn + (lane & 3) * 2;
#pragma unroll
            for (int nt = 0; nt < 4; nt++)
                *(float2*)(cp + nt * 8) = make_float2(acc[mi][nt][half * 2 + 0],
                                                      acc[mi][nt][half * 2 + 1]);
        }
}

// ===================== host =====================
extern "C" void kernel_launch(void* const* d_in, const int* in_sizes, int n_in,
                              void* d_out, int out_size)
{
    const float* x      = (const float*)d_in[0];
    const float* w1_s   = (const float*)d_in[1];
    const float* w2_s   = (const float*)d_in[2];
    const float* w3_s   = (const float*)d_in[3];
    const float* w1_r   = (const float*)d_in[4];
    const float* w2_r   = (const float*)d_in[5];
    const float* w3_r   = (const float*)d_in[6];
    const float* gate_w = (const float*)d_in[7];
    const float* out_w  = (const float*)d_in[8];
    float* out = (float*)d_out;

    cudaFuncSetAttribute(mm1_all_kernel, cudaFuncAttributeMaxDynamicSharedMemorySize, P1_SMEM);
    cudaFuncSetAttribute(mm2_all_kernel, cudaFuncAttributeMaxDynamicSharedMemorySize, P2_SMEM);
    cudaFuncSetAttribute(outproj_kernel, cudaFuncAttributeMaxDynamicSharedMemorySize, P2_SMEM);

    // 1: activations (+counter zeroing)
    convx_kernel<<<(NTOK * DIMC) / 2048, 256>>>(x);
    // 2: gate
    gate_kernel<<<NTOK / 8, 256>>>(x, gate_w);
    // 3: all 25 weight matrices
    {
        dim3 g(64, 64, 25);
        convt_all_kernel<<<g, 256>>>(w1_s, w3_s, w2_s, w1_r, w3_r, w2_r, out_w);
    }
    // 4: all 8 pass-1 GEMMs (256M tiles, 512 threads; profiled by ncu)
    {
        dim3 g(HIDC / 64, NTOK / 256, 8);
        mm1_all_kernel<<<g, 512, P1_SMEM>>>();
    }
    // 5: pass-2 — z=0 fused shared experts, z=1..6 routed
    {
        dim3 g(DIMC / 128, NTOK / 128, 7);
        mm2_all_kernel<<<g, 256, P2_SMEM>>>();
    }
    // 6: combine (+aux loss)
    convc3_kernel<<<(NTOK * DIMC) / 512, 256>>>(
        out_size > NTOK * DIMC ? out + (out_size - 1) : nullptr);
    // 7: out projection
    {
        dim3 g(DIMC / 128, NTOK / 128);
        outproj_kernel<<<g, 256, P2_SMEM>>>(out);
    }
}

// round 15
// speedup vs baseline: 1.0547x; 1.0547x over previous
#include <cuda_runtime.h>
#include <cuda_fp16.h>
#include <math.h>
#include <stdint.h>

typedef __half fp16;

#define NTOK 8192
#define DIMC 1024
#define HIDC 2048
#define NRE  6
#define E2   (2ull<<20)

#define W1S_OFF 0ull
#define W3S_OFF (4ull<<20)
#define W2S_OFF (8ull<<20)
#define W1R_OFF (12ull<<20)
#define W3R_OFF (24ull<<20)
#define W2R_OFF (36ull<<20)
#define OUTW_OFF (48ull<<20)
#define WT_TOTAL (49ull<<20)

__device__ fp16 g_wt[WT_TOTAL];                      // weights fp16 [N][K]
__device__ fp16 g_x[(size_t)NTOK * DIMC];            // activations fp16
__device__ fp16 g_hall[8ull * NTOK * HIDC];          // h per expert slice
__device__ float g_comb[(size_t)NTOK * DIMC];        // shared experts (fused sum)
__device__ float g_bufA[(size_t)NTOK * DIMC];        // routed top-1
__device__ float g_bufB[(size_t)NTOK * DIMC];        // routed top-2
__device__ fp16 g_hc[(size_t)NTOK * DIMC];           // combined fp16
__device__ int   g_list[NRE * NTOK];
__device__ float g_lw[NRE * NTOK];
__device__ int   g_lrank[NRE * NTOK];
__device__ int   g_cnt[NRE];     // zero-init (.bss); re-zeroed at end of outproj
__device__ int   g_top1[NRE];    // same
__device__ float g_psum[NRE];    // same

// ===================== helpers =====================
__device__ __forceinline__ uint32_t s2u(const void* p) {
    return (uint32_t)__cvta_generic_to_shared(p);
}
__device__ __forceinline__ void cpa(uint32_t s, const void* g) {
    asm volatile("cp.async.cg.shared.global [%0], [%1], 16;" :: "r"(s), "l"(g));
}
__device__ __forceinline__ void cpa_commit() {
    asm volatile("cp.async.commit_group;" ::: "memory");
}
__device__ __forceinline__ void ldsm4(uint32_t* r, uint32_t addr) {
    asm volatile("ldmatrix.sync.aligned.m8n8.x4.shared.b16 {%0,%1,%2,%3}, [%4];"
        : "=r"(r[0]), "=r"(r[1]), "=r"(r[2]), "=r"(r[3]) : "r"(addr));
}
__device__ __forceinline__ void mma16816(float* d, const uint32_t* a, const uint32_t* b) {
    asm volatile("mma.sync.aligned.m16n8k16.row.col.f32.f16.f16.f32 "
        "{%0,%1,%2,%3}, {%4,%5,%6,%7}, {%8,%9}, {%0,%1,%2,%3};"
        : "+f"(d[0]), "+f"(d[1]), "+f"(d[2]), "+f"(d[3])
        : "r"(a[0]), "r"(a[1]), "r"(a[2]), "r"(a[3]), "r"(b[0]), "r"(b[1]));
}

// ===================== gate + x-conversion fused =====================
// Each warp handles one token: computes gate logits AND writes fp16 x row.
__global__ void __launch_bounds__(256) gatex_kernel(const float* __restrict__ x,
                                                    const float* __restrict__ gw) {
    __shared__ float sgw[DIMC * NRE];
    int tid = threadIdx.x;
    for (int i = tid; i < DIMC * NRE; i += 256) sgw[i] = gw[i];
    __syncthreads();
    int warp = tid >> 5, lane = tid & 31;
    int token = blockIdx.x * 8 + warp;
    if (token >= NTOK) return;
    const float* xr = x + (size_t)token * DIMC;
    fp16* xo = g_x + (size_t)token * DIMC;
    float acc[NRE] = {0.f, 0.f, 0.f, 0.f, 0.f, 0.f};
    for (int k = lane * 2; k < DIMC; k += 64) {
        float2 xv = *(const float2*)(xr + k);
        *(uint32_t*)(xo + k) = *(uint32_t*)&__floats2half2_rn(xv.x, xv.y);
#pragma unroll
        for (int e = 0; e < NRE; e++)
            acc[e] += xv.x * sgw[k * NRE + e] + xv.y * sgw[(k + 1) * NRE + e];
    }
#pragma unroll
    for (int e = 0; e < NRE; e++)
#pragma unroll
        for (int o = 16; o > 0; o >>= 1)
            acc[e] += __shfl_xor_sync(0xffffffffu, acc[e], o);
    if (lane == 0) {
        int i0 = 0; float v0 = acc[0];
        for (int e = 1; e < NRE; e++) if (acc[e] > v0) { v0 = acc[e]; i0 = e; }
        int i1 = -1; float v1 = -1e30f;
        for (int e = 0; e < NRE; e++) if (e != i0 && acc[e] > v1) { v1 = acc[e]; i1 = e; }
        float e2 = expf(v1 - v0);
        float inv = 1.0f / (1.0f + e2);
        float w0 = inv, w1 = e2 * inv;
        float p[NRE]; float s = 0.f;
        for (int e = 0; e < NRE; e++) { p[e] = expf(acc[e] - v0); s += p[e]; }
        float is = 1.0f / s;
        for (int e = 0; e < NRE; e++) atomicAdd(&g_psum[e], p[e] * is);
        atomicAdd(&g_top1[i0], 1);
        int p0 = atomicAdd(&g_cnt[i0], 1);
        g_list[i0 * NTOK + p0] = token; g_lw[i0 * NTOK + p0] = w0; g_lrank[i0 * NTOK + p0] = 0;
        int p1 = atomicAdd(&g_cnt[i1], 1);
        g_list[i1 * NTOK + p1] = token; g_lw[i1 * NTOK + p1] = w1; g_lrank[i1 * NTOK + p1] = 1;
    }
}

__global__ void __launch_bounds__(256) convt_all_kernel(
    const float* w1_s, const float* w3_s, const float* w2_s,
    const float* w1_r, const float* w3_r, const float* w2_r,
    const float* out_w)
{
    __shared__ float t[32][33];
    int z = blockIdx.z;
    int K, N; const float* src; fp16* dst;
    if (z < 16) {
        K = DIMC; N = HIDC;
        if (z < 2)       { src = w1_s + (size_t)z * E2;        dst = g_wt + W1S_OFF + (size_t)z * E2; }
        else if (z < 4)  { int e = z - 2;  src = w3_s + (size_t)e * E2; dst = g_wt + W3S_OFF + (size_t)e * E2; }
        else if (z < 10) { int e = z - 4;  src = w1_r + (size_t)e * E2; dst = g_wt + W1R_OFF + (size_t)e * E2; }
        else             { int e = z - 10; src = w3_r + (size_t)e * E2; dst = g_wt + W3R_OFF + (size_t)e * E2; }
    } else if (z < 24) {
        K = HIDC; N = DIMC;
        if (z < 18) { int e = z - 16; src = w2_s + (size_t)e * E2; dst = g_wt + W2S_OFF + (size_t)e * E2; }
        else        { int e = z - 18; src = w2_r + (size_t)e * E2; dst = g_wt + W2R_OFF + (size_t)e * E2; }
    } else {
        K = DIMC; N = DIMC; src = out_w; dst = g_wt + OUTW_OFF;
    }
    int k0 = blockIdx.y * 32, n0 = blockIdx.x * 32;
    if (k0 >= K || n0 >= N) return;
    int tx = threadIdx.x & 31, ty = threadIdx.x >> 5;
#pragma unroll
    for (int i = 0; i < 4; i++)
        t[ty + i * 8][tx] = src[(size_t)(k0 + ty + i * 8) * N + n0 + tx];
    __syncthreads();
#pragma unroll
    for (int i = 0; i < 4; i++)
        dst[(size_t)(n0 + ty + i * 8) * K + k0 + tx] = __float2half_rn(t[tx][ty + i * 8]);
}

// comb + bufA + bufB -> fp16 ; block 0 thread 0 also writes aux loss
__global__ void __launch_bounds__(256) convc3_kernel(float* auxDst) {
    if (auxDst && blockIdx.x == 0 && threadIdx.x == 0) {
        float a = 0.f;
        for (int e = 0; e < NRE; e++) {
            float f = (float)g_top1[e] / (float)NTOK;
            float pm = g_psum[e] / (float)NTOK;
            a += f * pm;
        }
        *auxDst = 0.01f * (float)NRE * a;
    }
    size_t i = ((size_t)blockIdx.x * 256 + threadIdx.x) * 2;
    float2 a = *(const float2*)(g_comb + i);
    float2 b = *(const float2*)(g_bufA + i);
    float2 c = *(const float2*)(g_bufB + i);
    *(uint32_t*)(g_hc + i) = *(uint32_t*)&__floats2half2_rn(a.x + b.x + c.x,
                                                            a.y + b.y + c.y);
}

// ===================== mm1_all: all 8 pass-1 GEMMs, occ 2 (R13 config) =====================
#define P1_PITCH 144
#define P1_A  0
#define P1_B1 18432
#define P1_B3 27648
#define P1_STG 36864
#define P1_SIDX (3*P1_STG)           // 110592
#define P1_SMEM (P1_SIDX + 512)      // 111104

__global__ void __launch_bounds__(256, 2) mm1_all_kernel()
{
    extern __shared__ char smem[];
    const int z = blockIdx.z;
    const fp16* W1; const fp16* W3;
    const int* gidx; const float* gscale; int M;
    if (z < 2) {
        W1 = g_wt + W1S_OFF + (size_t)z * E2;
        W3 = g_wt + W3S_OFF + (size_t)z * E2;
        gidx = nullptr; gscale = nullptr; M = NTOK;
    } else {
        int e = z - 2;
        W1 = g_wt + W1R_OFF + (size_t)e * E2;
        W3 = g_wt + W3R_OFF + (size_t)e * E2;
        gidx = g_list + e * NTOK; gscale = g_lw + e * NTOK; M = g_cnt[e];
    }
    fp16* hout = g_hall + (size_t)z * NTOK * HIDC;

    const int mBase = blockIdx.y * 128;
    if (mBase >= M) return;
    const int nBase = blockIdx.x * 64;
    const uint32_t sb = s2u(smem);
    const int tid = threadIdx.x;

    int* sIdx = (int*)(smem + P1_SIDX);
    if (tid < 128) {
        int r = mBase + tid;
        sIdx[tid] = (r < M) ? (gidx ? gidx[r] : r) : 0;
    }
    __syncthreads();

    auto load = [&](int buf, int k0) {
        uint32_t su = sb + buf * P1_STG;
#pragma unroll
        for (int it = 0; it < 4; it++) {
            int idx = tid + it * 256;
            int row = idx >> 3, seg = idx & 7;
            uint32_t so = row * P1_PITCH + seg * 16;
            cpa(su + P1_A + so, g_x + (size_t)sIdx[row] * DIMC + k0 + seg * 8);
        }
#pragma unroll
        for (int it = 0; it < 2; it++) {
            int idx = tid + it * 256;
            int row = idx >> 3, seg = idx & 7;
            uint32_t so = row * P1_PITCH + seg * 16;
            size_t gw = (size_t)(nBase + row) * DIMC + k0 + seg * 8;
            cpa(su + P1_B1 + so, W1 + gw);
            cpa(su + P1_B3 + so, W3 + gw);
        }
        cpa_commit();
    };

    const int lane = tid & 31, wid = tid >> 5;
    const int wm = (wid & 3) * 32;
    const int wn = (wid >> 2) * 32;
    const int arow = (lane & 7) + ((lane >> 3) & 1) * 8;
    const int akh  = (lane >> 4) & 1;
    const int brow = (lane & 7) + ((lane >> 4) & 1) * 8;
    const int bkh  = (lane >> 3) & 1;

    float acc1[2][4][4], acc3[2][4][4];
#pragma unroll
    for (int i = 0; i < 2; i++)
#pragma unroll
        for (int j = 0; j < 4; j++)
#pragma unroll
            for (int k = 0; k < 4; k++) { acc1[i][j][k] = 0.f; acc3[i][j][k] = 0.f; }

    const int nc = DIMC / 64;   // 16
    load(0, 0);
    load(1, 64);
    for (int c = 0; c < nc; c++) {
        if (c + 1 < nc) asm volatile("cp.async.wait_group 1;" ::: "memory");
        else            asm volatile("cp.async.wait_group 0;" ::: "memory");
        __syncthreads();
        if (c + 2 < nc) load((c + 2) % 3, (c + 2) * 64);
        uint32_t su = sb + (c % 3) * P1_STG;
#pragma unroll
        for (int s = 0; s < 4; s++) {
            uint32_t a[2][4];
#pragma unroll
            for (int mi = 0; mi < 2; mi++) {
                uint32_t ao = (uint32_t)(wm + mi * 16 + arow) * P1_PITCH + s * 32 + akh * 16;
                ldsm4(a[mi], su + P1_A + ao);
            }
#pragma unroll
            for (int np = 0; np < 2; np++) {
                uint32_t b1[4], b3[4];
                uint32_t bo = (uint32_t)(wn + np * 16 + brow) * P1_PITCH + s * 32 + bkh * 16;
                ldsm4(b1, su + P1_B1 + bo);
                ldsm4(b3, su + P1_B3 + bo);
#pragma unroll
                for (int mi = 0; mi < 2; mi++)
#pragma unroll
                    for (int h = 0; h < 2; h++) {
                        int nt = np * 2 + h;
                        mma16816(acc1[mi][nt], a[mi], &b1[h * 2]);
                        mma16816(acc3[mi][nt], a[mi], &b3[h * 2]);
                    }
            }
        }
    }

#pragma unroll
    for (int mi = 0; mi < 2; mi++)
#pragma unroll
        for (int half = 0; half < 2; half++) {
            int slot = mBase + wm + mi * 16 + (lane >> 2) + half * 8;
            if (slot < M) {
                float sc = gscale ? gscale[slot] : 1.0f;
                size_t rb = (size_t)slot * HIDC + nBase + wn + (lane & 3) * 2;
#pragma unroll
                for (int nt = 0; nt < 4; nt++) {
                    float u0 = acc1[mi][nt][half * 2 + 0];
                    float u1 = acc1[mi][nt][half * 2 + 1];
                    float v0 = acc3[mi][nt][half * 2 + 0];
                    float v1 = acc3[mi][nt][half * 2 + 1];
                    float h0 = u0 / (1.f + __expf(-u0)) * v0 * sc;
                    float h1 = u1 / (1.f + __expf(-u1)) * v1 * sc;
                    __half2 hp = __floats2half2_rn(h0, h1);
                    *(uint32_t*)(hout + rb + nt * 8) = *(uint32_t*)&hp;
                }
            }
        }
}

// ===================== mm2_all: 7 z-slices (128x128, chunk 64, 3-stage, occ 2) =====================
#define P2_A 0
#define P2_B 18432
#define P2_STG 36864
#define P2_SMEM (3*P2_STG)   // 110592

__global__ void __launch_bounds__(256, 2) mm2_all_kernel()
{
    extern __shared__ char smem[];
    const int z = blockIdx.z;
    const int e = z - 1;
    const int nPass = (z == 0) ? 2 : 1;
    const int M = (z == 0) ? NTOK : g_cnt[e];
    const int mBase = blockIdx.y * 128;
    if (mBase >= M) return;
    const int nBase = blockIdx.x * 128;
    const uint32_t sb = s2u(smem);
    const int tid = threadIdx.x;

    const int lane = tid & 31, wid = tid >> 5;
    const int wm = (wid & 1) * 64;
    const int wn = (wid >> 1) * 32;
    const int arow = (lane & 7) + ((lane >> 3) & 1) * 8;
    const int akh  = (lane >> 4) & 1;
    const int brow = (lane & 7) + ((lane >> 4) & 1) * 8;
    const int bkh  = (lane >> 3) & 1;

    float acc[4][4][4];
#pragma unroll
    for (int i = 0; i < 4; i++)
#pragma unroll
        for (int j = 0; j < 4; j++)
#pragma unroll
            for (int k = 0; k < 4; k++) acc[i][j][k] = 0.f;

    for (int ss = 0; ss < nPass; ss++) {
        const fp16* A; const fp16* B;
        if (z == 0) {
            A = g_hall + (size_t)ss * NTOK * HIDC;
            B = g_wt + W2S_OFF + (size_t)ss * E2;
        } else {
            A = g_hall + (size_t)(2 + e) * NTOK * HIDC;
            B = g_wt + W2R_OFF + (size_t)e * E2;
        }
        auto load = [&](int buf, int k0) {
            uint32_t su = sb + buf * P2_STG;
#pragma unroll
            for (int it = 0; it < 4; it++) {
                int idx = tid + it * 256;
                int row = idx >> 3, seg = idx & 7;
                uint32_t so = row * 144 + seg * 16;
                int ar = mBase + row; if (ar >= M) ar = mBase;
                cpa(su + P2_A + so, A + (size_t)ar * HIDC + k0 + seg * 8);
                cpa(su + P2_B + so, B + (size_t)(nBase + row) * HIDC + k0 + seg * 8);
            }
            cpa_commit();
        };
        const int nc = HIDC / 64;
        load(0, 0);
        load(1, 64);
        for (int c = 0; c < nc; c++) {
            if (c + 1 < nc) asm volatile("cp.async.wait_group 1;" ::: "memory");
            else            asm volatile("cp.async.wait_group 0;" ::: "memory");
            __syncthreads();
            if (c + 2 < nc) load((c + 2) % 3, (c + 2) * 64);
            uint32_t su = sb + (c % 3) * P2_STG;
#pragma unroll
            for (int s = 0; s < 4; s++) {
                uint32_t a[4][4];
#pragma unroll
                for (int mi = 0; mi < 4; mi++) {
                    uint32_t ao = (uint32_t)(wm + mi * 16 + arow) * 144 + s * 32 + akh * 16;
                    ldsm4(a[mi], su + P2_A + ao);
                }
#pragma unroll
                for (int np = 0; np < 2; np++) {
                    uint32_t b[4];
                    uint32_t bo = (uint32_t)(wn + np * 16 + brow) * 144 + s * 32 + bkh * 16;
                    ldsm4(b, su + P2_B + bo);
#pragma unroll
                    for (int mi = 0; mi < 4; mi++)
#pragma unroll
                        for (int h = 0; h < 2; h++)
                            mma16816(acc[mi][np * 2 + h], a[mi], &b[h * 2]);
                }
            }
        }
        __syncthreads();
    }

#pragma unroll
    for (int mi = 0; mi < 4; mi++)
#pragma unroll
        for (int half = 0; half < 2; half++) {
            int slot = mBase + wm + mi * 16 + (lane >> 2) + half * 8;
            if (slot < M) {
                float* base; int t;
                if (z == 0) { base = g_comb; t = slot; }
                else {
                    t = g_list[e * NTOK + slot];
                    base = g_lrank[e * NTOK + slot] ? g_bufB : g_bufA;
                }
                float* cp = base + (size_t)t * DIMC + nBase + wn + (lane & 3) * 2;
#pragma unroll
                for (int nt = 0; nt < 4; nt++)
                    *(float2*)(cp + nt * 8) = make_float2(acc[mi][nt][half * 2 + 0],
                                                          acc[mi][nt][half * 2 + 1]);
            }
        }
}

// outproj: out = g_hc @ outw (K=1024); also re-zeroes gate counters for next call
__global__ void __launch_bounds__(256, 2) outproj_kernel(float* __restrict__ out)
{
    extern __shared__ char smem[];
    if (blockIdx.x == 0 && blockIdx.y == 0 && threadIdx.x < NRE) {
        g_cnt[threadIdx.x] = 0; g_top1[threadIdx.x] = 0; g_psum[threadIdx.x] = 0.f;
    }
    const int mBase = blockIdx.y * 128;
    const int nBase = blockIdx.x * 128;
    const fp16* B = g_wt + OUTW_OFF;
    const uint32_t sb = s2u(smem);
    const int tid = threadIdx.x;

    auto load = [&](int buf, int k0) {
        uint32_t su = sb + buf * P2_STG;
#pragma unroll
        for (int it = 0; it < 4; it++) {
            int idx = tid + it * 256;
            int row = idx >> 3, seg = idx & 7;
            uint32_t so = row * 144 + seg * 16;
            cpa(su + P2_A + so, g_hc + (size_t)(mBase + row) * DIMC + k0 + seg * 8);
            cpa(su + P2_B + so, B + (size_t)(nBase + row) * DIMC + k0 + seg * 8);
        }
        cpa_commit();
    };

    const int lane = tid & 31, wid = tid >> 5;
    const int wm = (wid & 1) * 64;
    const int wn = (wid >> 1) * 32;
    const int arow = (lane & 7) + ((lane >> 3) & 1) * 8;
    const int akh  = (lane >> 4) & 1;
    const int brow = (lane & 7) + ((lane >> 4) & 1) * 8;
    const int bkh  = (lane >> 3) & 1;

    float acc[4][4][4];
#pragma unroll
    for (int i = 0; i < 4; i++)
#pragma unroll
        for (int j = 0; j < 4; j++)
#pragma unroll
            for (int k = 0; k < 4; k++) acc[i][j][k] = 0.f;

    const int nc = DIMC / 64;
    load(0, 0);
    load(1, 64);
    for (int c = 0; c < nc; c++) {
        if (c + 1 < nc) asm volatile("cp.async.wait_group 1;" ::: "memory");
        else            asm volatile("cp.async.wait_group 0;" ::: "memory");
        __syncthreads();
        if (c + 2 < nc) load((c + 2) % 3, (c + 2) * 64);
        uint32_t su = sb + (c % 3) * P2_STG;
#pragma unroll
        for (int s = 0; s < 4; s++) {
            uint32_t a[4][4];
#pragma unroll
            for (int mi = 0; mi < 4; mi++) {
                uint32_t ao = (uint32_t)(wm + mi * 16 + arow) * 144 + s * 32 + akh * 16;
                ldsm4(a[mi], su + P2_A + ao);
            }
#pragma unroll
            for (int np = 0; np < 2; np++) {
                uint32_t b[4];
                uint32_t bo = (uint32_t)(wn + np * 16 + brow) * 144 + s * 32 + bkh * 16;
                ldsm4(b, su + P2_B + bo);
#pragma unroll
                for (int mi = 0; mi < 4; mi++)
#pragma unroll
                    for (int h = 0; h < 2; h++)
                        mma16816(acc[mi][np * 2 + h], a[mi], &b[h * 2]);
            }
        }
    }

#pragma unroll
    for (int mi = 0; mi < 4; mi++)
#pragma unroll
        for (int half = 0; half < 2; half++) {
            int t = mBase + wm + mi * 16 + (lane >> 2) + half * 8;
            float* cp = out + (size_t)t * DIMC + nBase + wn + (lane & 3) * 2;
#pragma unroll
            for (int nt = 0; nt < 4; nt++)
                *(float2*)(cp + nt * 8) = make_float2(acc[mi][nt][half * 2 + 0],
                                                      acc[mi][nt][half * 2 + 1]);
        }
}

// ===================== host =====================
extern "C" void kernel_launch(void* const* d_in, const int* in_sizes, int n_in,
                              void* d_out, int out_size)
{
    const float* x      = (const float*)d_in[0];
    const float* w1_s   = (const float*)d_in[1];
    const float* w2_s   = (const float*)d_in[2];
    const float* w3_s   = (const float*)d_in[3];
    const float* w1_r   = (const float*)d_in[4];
    const float* w2_r   = (const float*)d_in[5];
    const float* w3_r   = (const float*)d_in[6];
    const float* gate_w = (const float*)d_in[7];
    const float* out_w  = (const float*)d_in[8];
    float* out = (float*)d_out;

    cudaFuncSetAttribute(mm1_all_kernel, cudaFuncAttributeMaxDynamicSharedMemorySize, P1_SMEM);
    cudaFuncSetAttribute(mm2_all_kernel, cudaFuncAttributeMaxDynamicSharedMemorySize, P2_SMEM);
    cudaFuncSetAttribute(outproj_kernel, cudaFuncAttributeMaxDynamicSharedMemorySize, P2_SMEM);

    // 1: gate + x conversion fused (counters pre-zeroed: .bss init / prior call's outproj)
    gatex_kernel<<<NTOK / 8, 256>>>(x, gate_w);
    // 2: all 25 weight matrices
    {
        dim3 g(64, 64, 25);
        convt_all_kernel<<<g, 256>>>(w1_s, w3_s, w2_s, w1_r, w3_r, w2_r, out_w);
    }
    // 3: all 8 pass-1 GEMMs
    {
        dim3 g(HIDC / 64, NTOK / 128, 8);
        mm1_all_kernel<<<g, 256, P1_SMEM>>>();
    }
    // 4: pass-2 (profiled by ncu this round)
    {
        dim3 g(DIMC / 128, NTOK / 128, 7);
        mm2_all_kernel<<<g, 256, P2_SMEM>>>();
    }
    // 5: combine (+aux loss)
    convc3_kernel<<<(NTOK * DIMC) / 512, 256>>>(
        out_size > NTOK * DIMC ? out + (out_size - 1) : nullptr);
    // 6: out projection (+counter re-zero for next call)
    {
        dim3 g(DIMC / 128, NTOK / 128);
        outproj_kernel<<<g, 256, P2_SMEM>>>(out);
    }
}

// round 16
// speedup vs baseline: 1.1466x; 1.0871x over previous
#include <cuda_runtime.h>
#include <cuda_fp16.h>
#include <math.h>
#include <stdint.h>

typedef __half fp16;

#define NTOK 8192
#define DIMC 1024
#define HIDC 2048
#define NRE  6
#define E2   (2ull<<20)

#define W1S_OFF 0ull
#define W3S_OFF (4ull<<20)
#define W2S_OFF (8ull<<20)
#define W1R_OFF (12ull<<20)
#define W3R_OFF (24ull<<20)
#define W2R_OFF (36ull<<20)
#define OUTW_OFF (48ull<<20)
#define WT_TOTAL (49ull<<20)

__device__ fp16 g_wt[WT_TOTAL];                      // weights fp16 [N][K]
__device__ fp16 g_x[(size_t)NTOK * DIMC];            // activations fp16
__device__ fp16 g_hall[8ull * NTOK * HIDC];          // h per expert slice
__device__ float g_comb[(size_t)NTOK * DIMC];        // shared experts (fused sum)
__device__ float g_bufA[(size_t)NTOK * DIMC];        // routed top-1
__device__ float g_bufB[(size_t)NTOK * DIMC];        // routed top-2
__device__ fp16 g_hc[(size_t)NTOK * DIMC];           // combined fp16
__device__ int   g_list[NRE * NTOK];
__device__ float g_lw[NRE * NTOK];
__device__ int   g_lrank[NRE * NTOK];
__device__ int   g_cnt[NRE];     // zero-init (.bss); re-zeroed at end of outproj
__device__ int   g_top1[NRE];
__device__ float g_psum[NRE];

// ===================== helpers =====================
__device__ __forceinline__ uint32_t s2u(const void* p) {
    return (uint32_t)__cvta_generic_to_shared(p);
}
__device__ __forceinline__ void cpa(uint32_t s, const void* g) {
    asm volatile("cp.async.cg.shared.global [%0], [%1], 16;" :: "r"(s), "l"(g));
}
__device__ __forceinline__ void cpa_commit() {
    asm volatile("cp.async.commit_group;" ::: "memory");
}
__device__ __forceinline__ void ldsm4(uint32_t* r, uint32_t addr) {
    asm volatile("ldmatrix.sync.aligned.m8n8.x4.shared.b16 {%0,%1,%2,%3}, [%4];"
        : "=r"(r[0]), "=r"(r[1]), "=r"(r[2]), "=r"(r[3]) : "r"(addr));
}
__device__ __forceinline__ void mma16816(float* d, const uint32_t* a, const uint32_t* b) {
    asm volatile("mma.sync.aligned.m16n8k16.row.col.f32.f16.f16.f32 "
        "{%0,%1,%2,%3}, {%4,%5,%6,%7}, {%8,%9}, {%0,%1,%2,%3};"
        : "+f"(d[0]), "+f"(d[1]), "+f"(d[2]), "+f"(d[3])
        : "r"(a[0]), "r"(a[1]), "r"(a[2]), "r"(a[3]), "r"(b[0]), "r"(b[1]));
}

// ===================== gate + x-conversion fused =====================
__global__ void __launch_bounds__(256) gatex_kernel(const float* __restrict__ x,
                                                    const float* __restrict__ gw) {
    __shared__ float sgw[DIMC * NRE];
    int tid = threadIdx.x;
    for (int i = tid; i < DIMC * NRE; i += 256) sgw[i] = gw[i];
    __syncthreads();
    int warp = tid >> 5, lane = tid & 31;
    int token = blockIdx.x * 8 + warp;
    if (token >= NTOK) return;
    const float* xr = x + (size_t)token * DIMC;
    fp16* xo = g_x + (size_t)token * DIMC;
    float acc[NRE] = {0.f, 0.f, 0.f, 0.f, 0.f, 0.f};
    for (int k = lane * 2; k < DIMC; k += 64) {
        float2 xv = *(const float2*)(xr + k);
        *(uint32_t*)(xo + k) = *(uint32_t*)&__floats2half2_rn(xv.x, xv.y);
#pragma unroll
        for (int e = 0; e < NRE; e++)
            acc[e] += xv.x * sgw[k * NRE + e] + xv.y * sgw[(k + 1) * NRE + e];
    }
#pragma unroll
    for (int e = 0; e < NRE; e++)
#pragma unroll
        for (int o = 16; o > 0; o >>= 1)
            acc[e] += __shfl_xor_sync(0xffffffffu, acc[e], o);
    if (lane == 0) {
        int i0 = 0; float v0 = acc[0];
        for (int e = 1; e < NRE; e++) if (acc[e] > v0) { v0 = acc[e]; i0 = e; }
        int i1 = -1; float v1 = -1e30f;
        for (int e = 0; e < NRE; e++) if (e != i0 && acc[e] > v1) { v1 = acc[e]; i1 = e; }
        float e2 = expf(v1 - v0);
        float inv = 1.0f / (1.0f + e2);
        float w0 = inv, w1 = e2 * inv;
        float p[NRE]; float s = 0.f;
        for (int e = 0; e < NRE; e++) { p[e] = expf(acc[e] - v0); s += p[e]; }
        float is = 1.0f / s;
        for (int e = 0; e < NRE; e++) atomicAdd(&g_psum[e], p[e] * is);
        atomicAdd(&g_top1[i0], 1);
        int p0 = atomicAdd(&g_cnt[i0], 1);
        g_list[i0 * NTOK + p0] = token; g_lw[i0 * NTOK + p0] = w0; g_lrank[i0 * NTOK + p0] = 0;
        int p1 = atomicAdd(&g_cnt[i1], 1);
        g_list[i1 * NTOK + p1] = token; g_lw[i1 * NTOK + p1] = w1; g_lrank[i1 * NTOK + p1] = 1;
    }
}

// 64K x 32N tiles; vectorized 16B fp16 stores (128B per dst row segment)
__global__ void __launch_bounds__(256) convt_all_kernel(
    const float* w1_s, const float* w3_s, const float* w2_s,
    const float* w1_r, const float* w3_r, const float* w2_r,
    const float* out_w)
{
    __shared__ float t[64][33];
    int z = blockIdx.z;
    int K, N; const float* src; fp16* dst;
    if (z < 16) {
        K = DIMC; N = HIDC;
        if (z < 2)       { src = w1_s + (size_t)z * E2;        dst = g_wt + W1S_OFF + (size_t)z * E2; }
        else if (z < 4)  { int e = z - 2;  src = w3_s + (size_t)e * E2; dst = g_wt + W3S_OFF + (size_t)e * E2; }
        else if (z < 10) { int e = z - 4;  src = w1_r + (size_t)e * E2; dst = g_wt + W1R_OFF + (size_t)e * E2; }
        else             { int e = z - 10; src = w3_r + (size_t)e * E2; dst = g_wt + W3R_OFF + (size_t)e * E2; }
    } else if (z < 24) {
        K = HIDC; N = DIMC;
        if (z < 18) { int e = z - 16; src = w2_s + (size_t)e * E2; dst = g_wt + W2S_OFF + (size_t)e * E2; }
        else        { int e = z - 18; src = w2_r + (size_t)e * E2; dst = g_wt + W2R_OFF + (size_t)e * E2; }
    } else {
        K = DIMC; N = DIMC; src = out_w; dst = g_wt + OUTW_OFF;
    }
    int k0 = blockIdx.y * 64, n0 = blockIdx.x * 32;
    if (k0 >= K || n0 >= N) return;
    int tx = threadIdx.x & 31, ty = threadIdx.x >> 5;
#pragma unroll
    for (int i = 0; i < 8; i++)
        t[ty + i * 8][tx] = src[(size_t)(k0 + ty + i * 8) * N + n0 + tx];
    __syncthreads();
    int row = threadIdx.x >> 3, seg = threadIdx.x & 7;   // row<32, seg<8 (8 k each)
    __half2 h[4];
#pragma unroll
    for (int j = 0; j < 4; j++)
        h[j] = __floats2half2_rn(t[seg * 8 + j * 2][row], t[seg * 8 + j * 2 + 1][row]);
    *(uint4*)(dst + (size_t)(n0 + row) * K + k0 + seg * 8) = *(uint4*)h;
}

// comb + bufA + bufB -> fp16 ; block 0 thread 0 also writes aux loss
__global__ void __launch_bounds__(256) convc3_kernel(float* auxDst) {
    if (auxDst && blockIdx.x == 0 && threadIdx.x == 0) {
        float a = 0.f;
        for (int e = 0; e < NRE; e++) {
            float f = (float)g_top1[e] / (float)NTOK;
            float pm = g_psum[e] / (float)NTOK;
            a += f * pm;
        }
        *auxDst = 0.01f * (float)NRE * a;
    }
    size_t i = ((size_t)blockIdx.x * 256 + threadIdx.x) * 2;
    float2 a = *(const float2*)(g_comb + i);
    float2 b = *(const float2*)(g_bufA + i);
    float2 c = *(const float2*)(g_bufB + i);
    *(uint32_t*)(g_hc + i) = *(uint32_t*)&__floats2half2_rn(a.x + b.x + c.x,
                                                            a.y + b.y + c.y);
}

// ===================== mm1_all: all 8 pass-1 GEMMs, occ 2 =====================
#define P1_PITCH 144
#define P1_A  0
#define P1_B1 18432
#define P1_B3 27648
#define P1_STG 36864
#define P1_SIDX (3*P1_STG)           // 110592
#define P1_SMEM (P1_SIDX + 512)      // 111104

__global__ void __launch_bounds__(256, 2) mm1_all_kernel()
{
    extern __shared__ char smem[];
    const int z = blockIdx.z;
    const fp16* W1; const fp16* W3;
    const int* gidx; const float* gscale; int M;
    if (z < 2) {
        W1 = g_wt + W1S_OFF + (size_t)z * E2;
        W3 = g_wt + W3S_OFF + (size_t)z * E2;
        gidx = nullptr; gscale = nullptr; M = NTOK;
    } else {
        int e = z - 2;
        W1 = g_wt + W1R_OFF + (size_t)e * E2;
        W3 = g_wt + W3R_OFF + (size_t)e * E2;
        gidx = g_list + e * NTOK; gscale = g_lw + e * NTOK; M = g_cnt[e];
    }
    fp16* hout = g_hall + (size_t)z * NTOK * HIDC;

    const int mBase = blockIdx.y * 128;
    if (mBase >= M) return;
    const int nBase = blockIdx.x * 64;
    const uint32_t sb = s2u(smem);
    const int tid = threadIdx.x;

    int* sIdx = (int*)(smem + P1_SIDX);
    if (tid < 128) {
        int r = mBase + tid;
        sIdx[tid] = (r < M) ? (gidx ? gidx[r] : r) : 0;
    }
    __syncthreads();

    auto load = [&](int buf, int k0) {
        uint32_t su = sb + buf * P1_STG;
#pragma unroll
        for (int it = 0; it < 4; it++) {
            int idx = tid + it * 256;
            int row = idx >> 3, seg = idx & 7;
            uint32_t so = row * P1_PITCH + seg * 16;
            cpa(su + P1_A + so, g_x + (size_t)sIdx[row] * DIMC + k0 + seg * 8);
        }
#pragma unroll
        for (int it = 0; it < 2; it++) {
            int idx = tid + it * 256;
            int row = idx >> 3, seg = idx & 7;
            uint32_t so = row * P1_PITCH + seg * 16;
            size_t gw = (size_t)(nBase + row) * DIMC + k0 + seg * 8;
            cpa(su + P1_B1 + so, W1 + gw);
            cpa(su + P1_B3 + so, W3 + gw);
        }
        cpa_commit();
    };

    const int lane = tid & 31, wid = tid >> 5;
    const int wm = (wid & 3) * 32;
    const int wn = (wid >> 2) * 32;
    const int arow = (lane & 7) + ((lane >> 3) & 1) * 8;
    const int akh  = (lane >> 4) & 1;
    const int brow = (lane & 7) + ((lane >> 4) & 1) * 8;
    const int bkh  = (lane >> 3) & 1;

    float acc1[2][4][4], acc3[2][4][4];
#pragma unroll
    for (int i = 0; i < 2; i++)
#pragma unroll
        for (int j = 0; j < 4; j++)
#pragma unroll
            for (int k = 0; k < 4; k++) { acc1[i][j][k] = 0.f; acc3[i][j][k] = 0.f; }

    const int nc = DIMC / 64;   // 16
    load(0, 0);
    load(1, 64);
    for (int c = 0; c < nc; c++) {
        if (c + 1 < nc) asm volatile("cp.async.wait_group 1;" ::: "memory");
        else            asm volatile("cp.async.wait_group 0;" ::: "memory");
        __syncthreads();
        uint32_t su = sb + (c % 3) * P1_STG;

        auto step = [&](int s) {
            uint32_t a[2][4];
#pragma unroll
            for (int mi = 0; mi < 2; mi++) {
                uint32_t ao = (uint32_t)(wm + mi * 16 + arow) * P1_PITCH + s * 32 + akh * 16;
                ldsm4(a[mi], su + P1_A + ao);
            }
#pragma unroll
            for (int np = 0; np < 2; np++) {
                uint32_t b1[4], b3[4];
                uint32_t bo = (uint32_t)(wn + np * 16 + brow) * P1_PITCH + s * 32 + bkh * 16;
                ldsm4(b1, su + P1_B1 + bo);
                ldsm4(b3, su + P1_B3 + bo);
#pragma unroll
                for (int mi = 0; mi < 2; mi++)
#pragma unroll
                    for (int h = 0; h < 2; h++) {
                        int nt = np * 2 + h;
                        mma16816(acc1[mi][nt], a[mi], &b1[h * 2]);
                        mma16816(acc3[mi][nt], a[mi], &b3[h * 2]);
                    }
            }
        };

        step(0);                               // tensor work first...
        if (c + 2 < nc) load((c + 2) % 3, (c + 2) * 64);   // ...then prefetch issue
#pragma unroll
        for (int s = 1; s < 4; s++) step(s);
    }

#pragma unroll
    for (int mi = 0; mi < 2; mi++)
#pragma unroll
        for (int half = 0; half < 2; half++) {
            int slot = mBase + wm + mi * 16 + (lane >> 2) + half * 8;
            if (slot < M) {
                float sc = gscale ? gscale[slot] : 1.0f;
                size_t rb = (size_t)slot * HIDC + nBase + wn + (lane & 3) * 2;
#pragma unroll
                for (int nt = 0; nt < 4; nt++) {
                    float u0 = acc1[mi][nt][half * 2 + 0];
                    float u1 = acc1[mi][nt][half * 2 + 1];
                    float v0 = acc3[mi][nt][half * 2 + 0];
                    float v1 = acc3[mi][nt][half * 2 + 1];
                    float h0 = u0 / (1.f + __expf(-u0)) * v0 * sc;
                    float h1 = u1 / (1.f + __expf(-u1)) * v1 * sc;
                    __half2 hp = __floats2half2_rn(h0, h1);
                    *(uint32_t*)(hout + rb + nt * 8) = *(uint32_t*)&hp;
                }
            }
        }
}

// ===================== mm2_all: 7 z-slices (128x128, chunk 64, 3-stage, occ 2) =====================
#define P2_A 0
#define P2_B 18432
#define P2_STG 36864
#define P2_SMEM (3*P2_STG)   // 110592

__global__ void __launch_bounds__(256, 2) mm2_all_kernel()
{
    extern __shared__ char smem[];
    const int z = blockIdx.z;
    const int e = z - 1;
    const int nPass = (z == 0) ? 2 : 1;
    const int M = (z == 0) ? NTOK : g_cnt[e];
    const int mBase = blockIdx.y * 128;
    if (mBase >= M) return;
    const int nBase = blockIdx.x * 128;
    const uint32_t sb = s2u(smem);
    const int tid = threadIdx.x;

    const int lane = tid & 31, wid = tid >> 5;
    const int wm = (wid & 1) * 64;
    const int wn = (wid >> 1) * 32;
    const int arow = (lane & 7) + ((lane >> 3) & 1) * 8;
    const int akh  = (lane >> 4) & 1;
    const int brow = (lane & 7) + ((lane >> 4) & 1) * 8;
    const int bkh  = (lane >> 3) & 1;

    float acc[4][4][4];
#pragma unroll
    for (int i = 0; i < 4; i++)
#pragma unroll
        for (int j = 0; j < 4; j++)
#pragma unroll
            for (int k = 0; k < 4; k++) acc[i][j][k] = 0.f;

    for (int ss = 0; ss < nPass; ss++) {
        const fp16* A; const fp16* B;
        if (z == 0) {
            A = g_hall + (size_t)ss * NTOK * HIDC;
            B = g_wt + W2S_OFF + (size_t)ss * E2;
        } else {
            A = g_hall + (size_t)(2 + e) * NTOK * HIDC;
            B = g_wt + W2R_OFF + (size_t)e * E2;
        }
        auto load = [&](int buf, int k0) {
            uint32_t su = sb + buf * P2_STG;
#pragma unroll
            for (int it = 0; it < 4; it++) {
                int idx = tid + it * 256;
                int row = idx >> 3, seg = idx & 7;
                uint32_t so = row * 144 + seg * 16;
                int ar = mBase + row; if (ar >= M) ar = mBase;
                cpa(su + P2_A + so, A + (size_t)ar * HIDC + k0 + seg * 8);
                cpa(su + P2_B + so, B + (size_t)(nBase + row) * HIDC + k0 + seg * 8);
            }
            cpa_commit();
        };
        const int nc = HIDC / 64;
        load(0, 0);
        load(1, 64);
        for (int c = 0; c < nc; c++) {
            if (c + 1 < nc) asm volatile("cp.async.wait_group 1;" ::: "memory");
            else            asm volatile("cp.async.wait_group 0;" ::: "memory");
            __syncthreads();
            uint32_t su = sb + (c % 3) * P2_STG;

            auto step = [&](int s) {
                uint32_t a[4][4];
#pragma unroll
                for (int mi = 0; mi < 4; mi++) {
                    uint32_t ao = (uint32_t)(wm + mi * 16 + arow) * 144 + s * 32 + akh * 16;
                    ldsm4(a[mi], su + P2_A + ao);
                }
#pragma unroll
                for (int np = 0; np < 2; np++) {
                    uint32_t b[4];
                    uint32_t bo = (uint32_t)(wn + np * 16 + brow) * 144 + s * 32 + bkh * 16;
                    ldsm4(b, su + P2_B + bo);
#pragma unroll
                    for (int mi = 0; mi < 4; mi++)
#pragma unroll
                        for (int h = 0; h < 2; h++)
                            mma16816(acc[mi][np * 2 + h], a[mi], &b[h * 2]);
                }
            };

            step(0);
            if (c + 2 < nc) load((c + 2) % 3, (c + 2) * 64);
#pragma unroll
            for (int s = 1; s < 4; s++) step(s);
        }
        __syncthreads();
    }

#pragma unroll
    for (int mi = 0; mi < 4; mi++)
#pragma unroll
        for (int half = 0; half < 2; half++) {
            int slot = mBase + wm + mi * 16 + (lane >> 2) + half * 8;
            if (slot < M) {
                float* base; int t;
                if (z == 0) { base = g_comb; t = slot; }
                else {
                    t = g_list[e * NTOK + slot];
                    base = g_lrank[e * NTOK + slot] ? g_bufB : g_bufA;
                }
                float* cp = base + (size_t)t * DIMC + nBase + wn + (lane & 3) * 2;
#pragma unroll
                for (int nt = 0; nt < 4; nt++)
                    *(float2*)(cp + nt * 8) = make_float2(acc[mi][nt][half * 2 + 0],
                                                          acc[mi][nt][half * 2 + 1]);
            }
        }
}

// outproj: out = g_hc @ outw (K=1024); re-zeroes gate counters for next call
__global__ void __launch_bounds__(256, 2) outproj_kernel(float* __restrict__ out)
{
    extern __shared__ char smem[];
    if (blockIdx.x == 0 && blockIdx.y == 0 && threadIdx.x < NRE) {
        g_cnt[threadIdx.x] = 0; g_top1[threadIdx.x] = 0; g_psum[threadIdx.x] = 0.f;
    }
    const int mBase = blockIdx.y * 128;
    const int nBase = blockIdx.x * 128;
    const fp16* B = g_wt + OUTW_OFF;
    const uint32_t sb = s2u(smem);
    const int tid = threadIdx.x;

    auto load = [&](int buf, int k0) {
        uint32_t su = sb + buf * P2_STG;
#pragma unroll
        for (int it = 0; it < 4; it++) {
            int idx = tid + it * 256;
            int row = idx >> 3, seg = idx & 7;
            uint32_t so = row * 144 + seg * 16;
            cpa(su + P2_A + so, g_hc + (size_t)(mBase + row) * DIMC + k0 + seg * 8);
            cpa(su + P2_B + so, B + (size_t)(nBase + row) * DIMC + k0 + seg * 8);
        }
        cpa_commit();
    };

    const int lane = tid & 31, wid = tid >> 5;
    const int wm = (wid & 1) * 64;
    const int wn = (wid >> 1) * 32;
    const int arow = (lane & 7) + ((lane >> 3) & 1) * 8;
    const int akh  = (lane >> 4) & 1;
    const int brow = (lane & 7) + ((lane >> 4) & 1) * 8;
    const int bkh  = (lane >> 3) & 1;

    float acc[4][4][4];
#pragma unroll
    for (int i = 0; i < 4; i++)
#pragma unroll
        for (int j = 0; j < 4; j++)
#pragma unroll
            for (int k = 0; k < 4; k++) acc[i][j][k] = 0.f;

    const int nc = DIMC / 64;
    load(0, 0);
    load(1, 64);
    for (int c = 0; c < nc; c++) {
        if (c + 1 < nc) asm volatile("cp.async.wait_group 1;" ::: "memory");
        else            asm volatile("cp.async.wait_group 0;" ::: "memory");
        __syncthreads();
        uint32_t su = sb + (c % 3) * P2_STG;

        auto step = [&](int s) {
            uint32_t a[4][4];
#pragma unroll
            for (int mi = 0; mi < 4; mi++) {
                uint32_t ao = (uint32_t)(wm + mi * 16 + arow) * 144 + s * 32 + akh * 16;
                ldsm4(a[mi], su + P2_A + ao);
            }
#pragma unroll
            for (int np = 0; np < 2; np++) {
                uint32_t b[4];
                uint32_t bo = (uint32_t)(wn + np * 16 + brow) * 144 + s * 32 + bkh * 16;
                ldsm4(b, su + P2_B + bo);
#pragma unroll
                for (int mi = 0; mi < 4; mi++)
#pragma unroll
                    for (int h = 0; h < 2; h++)
                        mma16816(acc[mi][np * 2 + h], a[mi], &b[h * 2]);
            }
        };

        step(0);
        if (c + 2 < nc) load((c + 2) % 3, (c + 2) * 64);
#pragma unroll
        for (int s = 1; s < 4; s++) step(s);
    }

#pragma unroll
    for (int mi = 0; mi < 4; mi++)
#pragma unroll
        for (int half = 0; half < 2; half++) {
            int t = mBase + wm + mi * 16 + (lane >> 2) + half * 8;
            float* cp = out + (size_t)t * DIMC + nBase + wn + (lane & 3) * 2;
#pragma unroll
            for (int nt = 0; nt < 4; nt++)
                *(float2*)(cp + nt * 8) = make_float2(acc[mi][nt][half * 2 + 0],
                                                      acc[mi][nt][half * 2 + 1]);
        }
}

// ===================== host =====================
extern "C" void kernel_launch(void* const* d_in, const int* in_sizes, int n_in,
                              void* d_out, int out_size)
{
    const float* x      = (const float*)d_in[0];
    const float* w1_s   = (const float*)d_in[1];
    const float* w2_s   = (const float*)d_in[2];
    const float* w3_s   = (const float*)d_in[3];
    const float* w1_r   = (const float*)d_in[4];
    const float* w2_r   = (const float*)d_in[5];
    const float* w3_r   = (const float*)d_in[6];
    const float* gate_w = (const float*)d_in[7];
    const float* out_w  = (const float*)d_in[8];
    float* out = (float*)d_out;

    cudaFuncSetAttribute(mm1_all_kernel, cudaFuncAttributeMaxDynamicSharedMemorySize, P1_SMEM);
    cudaFuncSetAttribute(mm2_all_kernel, cudaFuncAttributeMaxDynamicSharedMemorySize, P2_SMEM);
    cudaFuncSetAttribute(outproj_kernel, cudaFuncAttributeMaxDynamicSharedMemorySize, P2_SMEM);

    // 1: gate + x conversion fused
    gatex_kernel<<<NTOK / 8, 256>>>(x, gate_w);
    // 2: all 25 weight matrices (64K x 32N tiles)
    {
        dim3 g(64, 32, 25);
        convt_all_kernel<<<g, 256>>>(w1_s, w3_s, w2_s, w1_r, w3_r, w2_r, out_w);
    }
    // 3: all 8 pass-1 GEMMs
    {
        dim3 g(HIDC / 64, NTOK / 128, 8);
        mm1_all_kernel<<<g, 256, P1_SMEM>>>();
    }
    // 4: pass-2
    {
        dim3 g(DIMC / 128, NTOK / 128, 7);
        mm2_all_kernel<<<g, 256, P2_SMEM>>>();
    }
    // 5: combine (+aux loss)
    convc3_kernel<<<(NTOK * DIMC) / 512, 256>>>(
        out_size > NTOK * DIMC ? out + (out_size - 1) : nullptr);
    // 6: out projection (+counter re-zero)
    {
        dim3 g(DIMC / 128, NTOK / 128);
        outproj_kernel<<<g, 256, P2_SMEM>>>(out);
    }
}

// round 17
// speedup vs baseline: 1.1907x; 1.0385x over previous
#include <cuda_runtime.h>
#include <cuda_fp16.h>
#include <math.h>
#include <stdint.h>

typedef __half fp16;

#define NTOK 8192
#define DIMC 1024
#define HIDC 2048
#define NRE  6
#define E2   (2ull<<20)

#define W1S_OFF 0ull
#define W3S_OFF (4ull<<20)
#define W2S_OFF (8ull<<20)
#define W1R_OFF (12ull<<20)
#define W3R_OFF (24ull<<20)
#define W2R_OFF (36ull<<20)
#define OUTW_OFF (48ull<<20)
#define WT_TOTAL (49ull<<20)

__device__ fp16 g_wt[WT_TOTAL];
__device__ fp16 g_x[(size_t)NTOK * DIMC];
__device__ fp16 g_hall[8ull * NTOK * HIDC];
__device__ float g_comb[(size_t)NTOK * DIMC];
__device__ float g_bufA[(size_t)NTOK * DIMC];
__device__ float g_bufB[(size_t)NTOK * DIMC];
__device__ fp16 g_hc[(size_t)NTOK * DIMC];
__device__ int   g_list[NRE * NTOK];
__device__ float g_lw[NRE * NTOK];
__device__ int   g_lrank[NRE * NTOK];
__device__ int   g_cnt[NRE];
__device__ int   g_top1[NRE];
__device__ float g_psum[NRE];

// ===================== helpers =====================
__device__ __forceinline__ uint32_t s2u(const void* p) {
    return (uint32_t)__cvta_generic_to_shared(p);
}
__device__ __forceinline__ void cpa(uint32_t s, const void* g) {
    asm volatile("cp.async.cg.shared.global [%0], [%1], 16;" :: "r"(s), "l"(g));
}
__device__ __forceinline__ void cpa_commit() {
    asm volatile("cp.async.commit_group;" ::: "memory");
}
__device__ __forceinline__ void ldsm4(uint32_t* r, uint32_t addr) {
    asm volatile("ldmatrix.sync.aligned.m8n8.x4.shared.b16 {%0,%1,%2,%3}, [%4];"
        : "=r"(r[0]), "=r"(r[1]), "=r"(r[2]), "=r"(r[3]) : "r"(addr));
}
__device__ __forceinline__ void mma16816(float* d, const uint32_t* a, const uint32_t* b) {
    asm volatile("mma.sync.aligned.m16n8k16.row.col.f32.f16.f16.f32 "
        "{%0,%1,%2,%3}, {%4,%5,%6,%7}, {%8,%9}, {%0,%1,%2,%3};"
        : "+f"(d[0]), "+f"(d[1]), "+f"(d[2]), "+f"(d[3])
        : "r"(a[0]), "r"(a[1]), "r"(a[2]), "r"(a[3]), "r"(b[0]), "r"(b[1]));
}

// ===================== gate + x-conversion fused =====================
__global__ void __launch_bounds__(256) gatex_kernel(const float* __restrict__ x,
                                                    const float* __restrict__ gw) {
    __shared__ float sgw[DIMC * NRE];
    int tid = threadIdx.x;
    for (int i = tid; i < DIMC * NRE; i += 256) sgw[i] = gw[i];
    __syncthreads();
    int warp = tid >> 5, lane = tid & 31;
    int token = blockIdx.x * 8 + warp;
    if (token >= NTOK) return;
    const float* xr = x + (size_t)token * DIMC;
    fp16* xo = g_x + (size_t)token * DIMC;
    float acc[NRE] = {0.f, 0.f, 0.f, 0.f, 0.f, 0.f};
    for (int k = lane * 2; k < DIMC; k += 64) {
        float2 xv = *(const float2*)(xr + k);
        *(uint32_t*)(xo + k) = *(uint32_t*)&__floats2half2_rn(xv.x, xv.y);
#pragma unroll
        for (int e = 0; e < NRE; e++)
            acc[e] += xv.x * sgw[k * NRE + e] + xv.y * sgw[(k + 1) * NRE + e];
    }
#pragma unroll
    for (int e = 0; e < NRE; e++)
#pragma unroll
        for (int o = 16; o > 0; o >>= 1)
            acc[e] += __shfl_xor_sync(0xffffffffu, acc[e], o);
    if (lane == 0) {
        int i0 = 0; float v0 = acc[0];
        for (int e = 1; e < NRE; e++) if (acc[e] > v0) { v0 = acc[e]; i0 = e; }
        int i1 = -1; float v1 = -1e30f;
        for (int e = 0; e < NRE; e++) if (e != i0 && acc[e] > v1) { v1 = acc[e]; i1 = e; }
        float e2 = expf(v1 - v0);
        float inv = 1.0f / (1.0f + e2);
        float w0 = inv, w1 = e2 * inv;
        float p[NRE]; float s = 0.f;
        for (int e = 0; e < NRE; e++) { p[e] = expf(acc[e] - v0); s += p[e]; }
        float is = 1.0f / s;
        for (int e = 0; e < NRE; e++) atomicAdd(&g_psum[e], p[e] * is);
        atomicAdd(&g_top1[i0], 1);
        int p0 = atomicAdd(&g_cnt[i0], 1);
        g_list[i0 * NTOK + p0] = token; g_lw[i0 * NTOK + p0] = w0; g_lrank[i0 * NTOK + p0] = 0;
        int p1 = atomicAdd(&g_cnt[i1], 1);
        g_list[i1 * NTOK + p1] = token; g_lw[i1 * NTOK + p1] = w1; g_lrank[i1 * NTOK + p1] = 1;
    }
}

// 64K x 32N tiles; vectorized 16B fp16 stores
__global__ void __launch_bounds__(256) convt_all_kernel(
    const float* w1_s, const float* w3_s, const float* w2_s,
    const float* w1_r, const float* w3_r, const float* w2_r,
    const float* out_w)
{
    __shared__ float t[64][33];
    int z = blockIdx.z;
    int K, N; const float* src; fp16* dst;
    if (z < 16) {
        K = DIMC; N = HIDC;
        if (z < 2)       { src = w1_s + (size_t)z * E2;        dst = g_wt + W1S_OFF + (size_t)z * E2; }
        else if (z < 4)  { int e = z - 2;  src = w3_s + (size_t)e * E2; dst = g_wt + W3S_OFF + (size_t)e * E2; }
        else if (z < 10) { int e = z - 4;  src = w1_r + (size_t)e * E2; dst = g_wt + W1R_OFF + (size_t)e * E2; }
        else             { int e = z - 10; src = w3_r + (size_t)e * E2; dst = g_wt + W3R_OFF + (size_t)e * E2; }
    } else if (z < 24) {
        K = HIDC; N = DIMC;
        if (z < 18) { int e = z - 16; src = w2_s + (size_t)e * E2; dst = g_wt + W2S_OFF + (size_t)e * E2; }
        else        { int e = z - 18; src = w2_r + (size_t)e * E2; dst = g_wt + W2R_OFF + (size_t)e * E2; }
    } else {
        K = DIMC; N = DIMC; src = out_w; dst = g_wt + OUTW_OFF;
    }
    int k0 = blockIdx.y * 64, n0 = blockIdx.x * 32;
    if (k0 >= K || n0 >= N) return;
    int tx = threadIdx.x & 31, ty = threadIdx.x >> 5;
#pragma unroll
    for (int i = 0; i < 8; i++)
        t[ty + i * 8][tx] = src[(size_t)(k0 + ty + i * 8) * N + n0 + tx];
    __syncthreads();
    int row = threadIdx.x >> 3, seg = threadIdx.x & 7;
    __half2 h[4];
#pragma unroll
    for (int j = 0; j < 4; j++)
        h[j] = __floats2half2_rn(t[seg * 8 + j * 2][row], t[seg * 8 + j * 2 + 1][row]);
    *(uint4*)(dst + (size_t)(n0 + row) * K + k0 + seg * 8) = *(uint4*)h;
}

// comb + bufA + bufB -> fp16 ; block 0 thread 0 also writes aux loss
__global__ void __launch_bounds__(256) convc3_kernel(float* auxDst) {
    if (auxDst && blockIdx.x == 0 && threadIdx.x == 0) {
        float a = 0.f;
        for (int e = 0; e < NRE; e++) {
            float f = (float)g_top1[e] / (float)NTOK;
            float pm = g_psum[e] / (float)NTOK;
            a += f * pm;
        }
        *auxDst = 0.01f * (float)NRE * a;
    }
    size_t i = ((size_t)blockIdx.x * 256 + threadIdx.x) * 2;
    float2 a = *(const float2*)(g_comb + i);
    float2 b = *(const float2*)(g_bufA + i);
    float2 c = *(const float2*)(g_bufB + i);
    *(uint32_t*)(g_hc + i) = *(uint32_t*)&__floats2half2_rn(a.x + b.x + c.x,
                                                            a.y + b.y + c.y);
}

// ===================== mm1_all: all 8 pass-1 GEMMs, occ 2 =====================
#define P1_PITCH 144
#define P1_A  0
#define P1_B1 18432
#define P1_B3 27648
#define P1_STG 36864
#define P1_SIDX (3*P1_STG)           // 110592
#define P1_SMEM (P1_SIDX + 512)      // 111104

__global__ void __launch_bounds__(256, 2) mm1_all_kernel()
{
    extern __shared__ char smem[];
    const int z = blockIdx.z;
    const fp16* W1; const fp16* W3;
    const int* gidx; const float* gscale; int M;
    if (z < 2) {
        W1 = g_wt + W1S_OFF + (size_t)z * E2;
        W3 = g_wt + W3S_OFF + (size_t)z * E2;
        gidx = nullptr; gscale = nullptr; M = NTOK;
    } else {
        int e = z - 2;
        W1 = g_wt + W1R_OFF + (size_t)e * E2;
        W3 = g_wt + W3R_OFF + (size_t)e * E2;
        gidx = g_list + e * NTOK; gscale = g_lw + e * NTOK; M = g_cnt[e];
    }
    fp16* hout = g_hall + (size_t)z * NTOK * HIDC;

    const int mBase = blockIdx.y * 128;
    if (mBase >= M) return;
    const int nBase = blockIdx.x * 64;
    const uint32_t sb = s2u(smem);
    const int tid = threadIdx.x;

    int* sIdx = (int*)(smem + P1_SIDX);
    if (tid < 128) {
        int r = mBase + tid;
        sIdx[tid] = (r < M) ? (gidx ? gidx[r] : r) : 0;
    }
    __syncthreads();

    auto loadA = [&](int buf, int k0) {
        uint32_t su = sb + buf * P1_STG;
#pragma unroll
        for (int it = 0; it < 4; it++) {
            int idx = tid + it * 256;
            int row = idx >> 3, seg = idx & 7;
            uint32_t so = row * P1_PITCH + seg * 16;
            cpa(su + P1_A + so, g_x + (size_t)sIdx[row] * DIMC + k0 + seg * 8);
        }
    };
    auto loadB = [&](int buf, int k0) {
        uint32_t su = sb + buf * P1_STG;
#pragma unroll
        for (int it = 0; it < 2; it++) {
            int idx = tid + it * 256;
            int row = idx >> 3, seg = idx & 7;
            uint32_t so = row * P1_PITCH + seg * 16;
            size_t gw = (size_t)(nBase + row) * DIMC + k0 + seg * 8;
            cpa(su + P1_B1 + so, W1 + gw);
            cpa(su + P1_B3 + so, W3 + gw);
        }
        cpa_commit();
    };

    const int lane = tid & 31, wid = tid >> 5;
    const int wm = (wid & 3) * 32;
    const int wn = (wid >> 2) * 32;
    const int arow = (lane & 7) + ((lane >> 3) & 1) * 8;
    const int akh  = (lane >> 4) & 1;
    const int brow = (lane & 7) + ((lane >> 4) & 1) * 8;
    const int bkh  = (lane >> 3) & 1;

    float acc1[2][4][4], acc3[2][4][4];
#pragma unroll
    for (int i = 0; i < 2; i++)
#pragma unroll
        for (int j = 0; j < 4; j++)
#pragma unroll
            for (int k = 0; k < 4; k++) { acc1[i][j][k] = 0.f; acc3[i][j][k] = 0.f; }

    const int nc = DIMC / 64;   // 16
    loadA(0, 0); loadB(0, 0);
    loadA(1, 64); loadB(1, 64);
    for (int c = 0; c < nc; c++) {
        if (c + 1 < nc) asm volatile("cp.async.wait_group 1;" ::: "memory");
        else            asm volatile("cp.async.wait_group 0;" ::: "memory");
        __syncthreads();
        uint32_t su = sb + (c % 3) * P1_STG;

        auto step = [&](int s) {
            uint32_t a[2][4];
#pragma unroll
            for (int mi = 0; mi < 2; mi++) {
                uint32_t ao = (uint32_t)(wm + mi * 16 + arow) * P1_PITCH + s * 32 + akh * 16;
                ldsm4(a[mi], su + P1_A + ao);
            }
#pragma unroll
            for (int np = 0; np < 2; np++) {
                uint32_t b1[4], b3[4];
                uint32_t bo = (uint32_t)(wn + np * 16 + brow) * P1_PITCH + s * 32 + bkh * 16;
                ldsm4(b1, su + P1_B1 + bo);
                ldsm4(b3, su + P1_B3 + bo);
#pragma unroll
                for (int mi = 0; mi < 2; mi++)
#pragma unroll
                    for (int h = 0; h < 2; h++) {
                        int nt = np * 2 + h;
                        mma16816(acc1[mi][nt], a[mi], &b1[h * 2]);
                        mma16816(acc3[mi][nt], a[mi], &b3[h * 2]);
                    }
            }
        };

        step(0);
        if (c + 2 < nc) loadA((c + 2) % 3, (c + 2) * 64);   // A prefetch after step 0
        step(1);
        if (c + 2 < nc) loadB((c + 2) % 3, (c + 2) * 64);   // B prefetch after step 1
        step(2);
        step(3);
    }

#pragma unroll
    for (int mi = 0; mi < 2; mi++)
#pragma unroll
        for (int half = 0; half < 2; half++) {
            int slot = mBase + wm + mi * 16 + (lane >> 2) + half * 8;
            if (slot < M) {
                float sc = gscale ? gscale[slot] : 1.0f;
                size_t rb = (size_t)slot * HIDC + nBase + wn + (lane & 3) * 2;
#pragma unroll
                for (int nt = 0; nt < 4; nt++) {
                    float u0 = acc1[mi][nt][half * 2 + 0];
                    float u1 = acc1[mi][nt][half * 2 + 1];
                    float v0 = acc3[mi][nt][half * 2 + 0];
                    float v1 = acc3[mi][nt][half * 2 + 1];
                    float h0 = u0 / (1.f + __expf(-u0)) * v0 * sc;
                    float h1 = u1 / (1.f + __expf(-u1)) * v1 * sc;
                    __half2 hp = __floats2half2_rn(h0, h1);
                    *(uint32_t*)(hout + rb + nt * 8) = *(uint32_t*)&hp;
                }
            }
        }
}

// ===================== mm2_all: 7 z-slices (128x128, chunk 64, 3-stage, occ 2) =====================
#define P2_A 0
#define P2_B 18432
#define P2_STG 36864
#define P2_SMEM (3*P2_STG)   // 110592

__global__ void __launch_bounds__(256, 2) mm2_all_kernel()
{
    extern __shared__ char smem[];
    const int z = blockIdx.z;
    const int e = z - 1;
    const int nPass = (z == 0) ? 2 : 1;
    const int M = (z == 0) ? NTOK : g_cnt[e];
    const int mBase = blockIdx.y * 128;
    if (mBase >= M) return;
    const int nBase = blockIdx.x * 128;
    const uint32_t sb = s2u(smem);
    const int tid = threadIdx.x;

    const int lane = tid & 31, wid = tid >> 5;
    const int wm = (wid & 1) * 64;
    const int wn = (wid >> 1) * 32;
    const int arow = (lane & 7) + ((lane >> 3) & 1) * 8;
    const int akh  = (lane >> 4) & 1;
    const int brow = (lane & 7) + ((lane >> 4) & 1) * 8;
    const int bkh  = (lane >> 3) & 1;

    float acc[4][4][4];
#pragma unroll
    for (int i = 0; i < 4; i++)
#pragma unroll
        for (int j = 0; j < 4; j++)
#pragma unroll
            for (int k = 0; k < 4; k++) acc[i][j][k] = 0.f;

    for (int ss = 0; ss < nPass; ss++) {
        const fp16* A; const fp16* B;
        if (z == 0) {
            A = g_hall + (size_t)ss * NTOK * HIDC;
            B = g_wt + W2S_OFF + (size_t)ss * E2;
        } else {
            A = g_hall + (size_t)(2 + e) * NTOK * HIDC;
            B = g_wt + W2R_OFF + (size_t)e * E2;
        }
        auto loadA = [&](int buf, int k0) {
            uint32_t su = sb + buf * P2_STG;
#pragma unroll
            for (int it = 0; it < 4; it++) {
                int idx = tid + it * 256;
                int row = idx >> 3, seg = idx & 7;
                uint32_t so = row * 144 + seg * 16;
                int ar = mBase + row; if (ar >= M) ar = mBase;
                cpa(su + P2_A + so, A + (size_t)ar * HIDC + k0 + seg * 8);
            }
        };
        auto loadB = [&](int buf, int k0) {
            uint32_t su = sb + buf * P2_STG;
#pragma unroll
            for (int it = 0; it < 4; it++) {
                int idx = tid + it * 256;
                int row = idx >> 3, seg = idx & 7;
                uint32_t so = row * 144 + seg * 16;
                cpa(su + P2_B + so, B + (size_t)(nBase + row) * HIDC + k0 + seg * 8);
            }
            cpa_commit();
        };
        const int nc = HIDC / 64;
        loadA(0, 0); loadB(0, 0);
        loadA(1, 64); loadB(1, 64);
        for (int c = 0; c < nc; c++) {
            if (c + 1 < nc) asm volatile("cp.async.wait_group 1;" ::: "memory");
            else            asm volatile("cp.async.wait_group 0;" ::: "memory");
            __syncthreads();
            uint32_t su = sb + (c % 3) * P2_STG;

            auto step = [&](int s) {
                uint32_t a[4][4];
#pragma unroll
                for (int mi = 0; mi < 4; mi++) {
                    uint32_t ao = (uint32_t)(wm + mi * 16 + arow) * 144 + s * 32 + akh * 16;
                    ldsm4(a[mi], su + P2_A + ao);
                }
#pragma unroll
                for (int np = 0; np < 2; np++) {
                    uint32_t b[4];
                    uint32_t bo = (uint32_t)(wn + np * 16 + brow) * 144 + s * 32 + bkh * 16;
                    ldsm4(b, su + P2_B + bo);
#pragma unroll
                    for (int mi = 0; mi < 4; mi++)
#pragma unroll
                        for (int h = 0; h < 2; h++)
                            mma16816(acc[mi][np * 2 + h], a[mi], &b[h * 2]);
                }
            };

            step(0);
            if (c + 2 < nc) loadA((c + 2) % 3, (c + 2) * 64);
            step(1);
            if (c + 2 < nc) loadB((c + 2) % 3, (c + 2) * 64);
            step(2);
            step(3);
        }
        __syncthreads();
    }

#pragma unroll
    for (int mi = 0; mi < 4; mi++)
#pragma unroll
        for (int half = 0; half < 2; half++) {
            int slot = mBase + wm + mi * 16 + (lane >> 2) + half * 8;
            if (slot < M) {
                float* base; int t;
                if (z == 0) { base = g_comb; t = slot; }
                else {
                    t = g_list[e * NTOK + slot];
                    base = g_lrank[e * NTOK + slot] ? g_bufB : g_bufA;
                }
                float* cp = base + (size_t)t * DIMC + nBase + wn + (lane & 3) * 2;
#pragma unroll
                for (int nt = 0; nt < 4; nt++)
                    *(float2*)(cp + nt * 8) = make_float2(acc[mi][nt][half * 2 + 0],
                                                          acc[mi][nt][half * 2 + 1]);
            }
        }
}

// outproj: out = g_hc @ outw (K=1024); re-zeroes gate counters for next call
__global__ void __launch_bounds__(256, 2) outproj_kernel(float* __restrict__ out)
{
    extern __shared__ char smem[];
    if (blockIdx.x == 0 && blockIdx.y == 0 && threadIdx.x < NRE) {
        g_cnt[threadIdx.x] = 0; g_top1[threadIdx.x] = 0; g_psum[threadIdx.x] = 0.f;
    }
    const int mBase = blockIdx.y * 128;
    const int nBase = blockIdx.x * 128;
    const fp16* B = g_wt + OUTW_OFF;
    const uint32_t sb = s2u(smem);
    const int tid = threadIdx.x;

    auto loadA = [&](int buf, int k0) {
        uint32_t su = sb + buf * P2_STG;
#pragma unroll
        for (int it = 0; it < 4; it++) {
            int idx = tid + it * 256;
            int row = idx >> 3, seg = idx & 7;
            uint32_t so = row * 144 + seg * 16;
            cpa(su + P2_A + so, g_hc + (size_t)(mBase + row) * DIMC + k0 + seg * 8);
        }
    };
    auto loadB = [&](int buf, int k0) {
        uint32_t su = sb + buf * P2_STG;
#pragma unroll
        for (int it = 0; it < 4; it++) {
            int idx = tid + it * 256;
            int row = idx >> 3, seg = idx & 7;
            uint32_t so = row * 144 + seg * 16;
            cpa(su + P2_B + so, B + (size_t)(nBase + row) * DIMC + k0 + seg * 8);
        }
        cpa_commit();
    };

    const int lane = tid & 31, wid = tid >> 5;
    const int wm = (wid & 1) * 64;
    const int wn = (wid >> 1) * 32;
    const int arow = (lane & 7) + ((lane >> 3) & 1) * 8;
    const int akh  = (lane >> 4) & 1;
    const int brow = (lane & 7) + ((lane >> 4) & 1) * 8;
    const int bkh  = (lane >> 3) & 1;

    float acc[4][4][4];
#pragma unroll
    for (int i = 0; i < 4; i++)
#pragma unroll
        for (int j = 0; j < 4; j++)
#pragma unroll
            for (int k = 0; k < 4; k++) acc[i][j][k] = 0.f;

    const int nc = DIMC / 64;
    loadA(0, 0); loadB(0, 0);
    loadA(1, 64); loadB(1, 64);
    for (int c = 0; c < nc; c++) {
        if (c + 1 < nc) asm volatile("cp.async.wait_group 1;" ::: "memory");
        else            asm volatile("cp.async.wait_group 0;" ::: "memory");
        __syncthreads();
        uint32_t su = sb + (c % 3) * P2_STG;

        auto step = [&](int s) {
            uint32_t a[4][4];
#pragma unroll
            for (int mi = 0; mi < 4; mi++) {
                uint32_t ao = (uint32_t)(wm + mi * 16 + arow) * 144 + s * 32 + akh * 16;
                ldsm4(a[mi], su + P2_A + ao);
            }
#pragma unroll
            for (int np = 0; np < 2; np++) {
                uint32_t b[4];
                uint32_t bo = (uint32_t)(wn + np * 16 + brow) * 144 + s * 32 + bkh * 16;
                ldsm4(b, su + P2_B + bo);
#pragma unroll
                for (int mi = 0; mi < 4; mi++)
#pragma unroll
                    for (int h = 0; h < 2; h++)
                        mma16816(acc[mi][np * 2 + h], a[mi], &b[h * 2]);
            }
        };

        step(0);
        if (c + 2 < nc) loadA((c + 2) % 3, (c + 2) * 64);
        step(1);
        if (c + 2 < nc) loadB((c + 2) % 3, (c + 2) * 64);
        step(2);
        step(3);
    }

#pragma unroll
    for (int mi = 0; mi < 4; mi++)
#pragma unroll
        for (int half = 0; half < 2; half++) {
            int t = mBase + wm + mi * 16 + (lane >> 2) + half * 8;
            float* cp = out + (size_t)t * DIMC + nBase + wn + (lane & 3) * 2;
#pragma unroll
            for (int nt = 0; nt < 4; nt++)
                *(float2*)(cp + nt * 8) = make_float2(acc[mi][nt][half * 2 + 0],
                                                      acc[mi][nt][half * 2 + 1]);
        }
}

// ===================== host =====================
extern "C" void kernel_launch(void* const* d_in, const int* in_sizes, int n_in,
                              void* d_out, int out_size)
{
    const float* x      = (const float*)d_in[0];
    const float* w1_s   = (const float*)d_in[1];
    const float* w2_s   = (const float*)d_in[2];
    const float* w3_s   = (const float*)d_in[3];
    const float* w1_r   = (const float*)d_in[4];
    const float* w2_r   = (const float*)d_in[5];
    const float* w3_r   = (const float*)d_in[6];
    const float* gate_w = (const float*)d_in[7];
    const float* out_w  = (const float*)d_in[8];
    float* out = (float*)d_out;

    cudaFuncSetAttribute(mm1_all_kernel, cudaFuncAttributeMaxDynamicSharedMemorySize, P1_SMEM);
    cudaFuncSetAttribute(mm2_all_kernel, cudaFuncAttributeMaxDynamicSharedMemorySize, P2_SMEM);
    cudaFuncSetAttribute(outproj_kernel, cudaFuncAttributeMaxDynamicSharedMemorySize, P2_SMEM);

    // 1: gate + x conversion fused
    gatex_kernel<<<NTOK / 8, 256>>>(x, gate_w);
    // 2: all 25 weight matrices
    {
        dim3 g(64, 32, 25);
        convt_all_kernel<<<g, 256>>>(w1_s, w3_s, w2_s, w1_r, w3_r, w2_r, out_w);
    }
    // 3: all 8 pass-1 GEMMs
    {
        dim3 g(HIDC / 64, NTOK / 128, 8);
        mm1_all_kernel<<<g, 256, P1_SMEM>>>();
    }
    // 4: pass-2
    {
        dim3 g(DIMC / 128, NTOK / 128, 7);
        mm2_all_kernel<<<g, 256, P2_SMEM>>>();
    }
    // 5: combine (+aux loss)
    convc3_kernel<<<(NTOK * DIMC) / 512, 256>>>(
        out_size > NTOK * DIMC ? out + (out_size - 1) : nullptr);
    // 6: out projection (+counter re-zero)
    {
        dim3 g(DIMC / 128, NTOK / 128);
        outproj_kernel<<<g, 256, P2_SMEM>>>(out);
    }
}